// round 12
// baseline (speedup 1.0000x reference)
#include <cuda_runtime.h>
#include <cuda_bf16.h>
#include <cstdint>

#define N_NODES 50000
#define HID 256
#define NCLS 40
#define E_MAX 1000000
#define KT 768                    // 3 * 256 split-K
#define FULL_MASK 0xFFFFFFFFu
#define WSLOT 196608              // 256*768 bf16 per weight slot

// ---------------- scratch (device globals; no allocations allowed) ----------
__device__ float          g_h[(size_t)N_NODES * HID];      // h = A' @ W' (fp32)
__device__ __nv_bfloat16  g_aexp[(size_t)N_NODES * KT];    // split A operand
__device__ __nv_bfloat16  g_wexp[4 * WSLOT];               // split weights, n-major
__device__ float g_ssrc[N_NODES];
__device__ float g_sdst[N_NODES];
__device__ int   g_deg[N_NODES];
__device__ int   g_offs[N_NODES + 1];
__device__ int   g_cursor[N_NODES];
__device__ int   g_csr[E_MAX];
__device__ int   g_bsum[64];
__device__ int   g_bbase[64];
__device__ int   g_idx64;

// ---------------- edge index access (dtype-agnostic) ------------------------
__device__ __forceinline__ int edge_val(const void* e, long long i) {
    return g_idx64 ? (int)((const long long*)e)[i] : ((const int*)e)[i];
}

// ---------------- CSR construction ------------------------------------------
__global__ void detect_and_init(const void* edge, int E) {
    int idx = blockIdx.x * blockDim.x + threadIdx.x;
    if (idx < N_NODES) g_deg[idx] = 1;  // self-loop
    if (idx == 0) {
        const long long* p = (const long long*)edge;
        int n = E < 1024 ? E : 1024;
        int ok = 1;
        for (int i = 0; i < n; i++) {
            long long v = p[i];
            if (v < 0 || v >= N_NODES) { ok = 0; break; }
        }
        g_idx64 = ok;
    }
}

__global__ void hist_kernel(const void* edge, int E) {
    int i = blockIdx.x * blockDim.x + threadIdx.x;
    if (i < E) atomicAdd(&g_deg[edge_val(edge, (long long)E + i)], 1);
}

__global__ void scan1_kernel() {
    __shared__ int sh[1024];
    int t = threadIdx.x;
    int i = blockIdx.x * 1024 + t;
    int v = (i < N_NODES) ? g_deg[i] : 0;
    sh[t] = v;
    __syncthreads();
    #pragma unroll
    for (int off = 1; off < 1024; off <<= 1) {
        int add = (t >= off) ? sh[t - off] : 0;
        __syncthreads();
        sh[t] += add;
        __syncthreads();
    }
    if (i < N_NODES) g_offs[i] = sh[t] - v;
    if (t == 1023) g_bsum[blockIdx.x] = sh[1023];
}

__global__ void scan2_kernel(int nb) {
    __shared__ int sh[64];
    int t = threadIdx.x;
    int v = (t < nb) ? g_bsum[t] : 0;
    sh[t] = v;
    __syncthreads();
    #pragma unroll
    for (int off = 1; off < 64; off <<= 1) {
        int add = (t >= off) ? sh[t - off] : 0;
        __syncthreads();
        sh[t] += add;
        __syncthreads();
    }
    g_bbase[t] = sh[t] - v;
    if (t == nb - 1) g_offs[N_NODES] = sh[t];
}

__global__ void scan3_kernel() {
    int i = blockIdx.x * blockDim.x + threadIdx.x;
    if (i < N_NODES) {
        int o = g_offs[i] + g_bbase[i >> 10];
        g_offs[i] = o;
        g_cursor[i] = o;
    }
}

__global__ void scatter_kernel(const void* edge, int E) {
    int i = blockIdx.x * blockDim.x + threadIdx.x;
    if (i < E) {
        int s = edge_val(edge, i);
        int d = edge_val(edge, (long long)E + i);
        g_csr[atomicAdd(&g_cursor[d], 1)] = s;
    } else if (i < E + N_NODES) {
        int v = i - E;
        g_csr[atomicAdd(&g_cursor[v], 1)] = v;
    }
}

__global__ void clear_scores_kernel() {
    int i = blockIdx.x * blockDim.x + threadIdx.x;
    if (i < N_NODES) { g_ssrc[i] = 0.f; g_sdst[i] = 0.f; }
}

// ---------------- split conversions ------------------------------------------
// A' row layout: [hi(256) | hi(256) | lo(256)]
__global__ void convert_split_kernel(const float* __restrict__ A,
                                     __nv_bfloat16* __restrict__ out, int M) {
    int i = blockIdx.x * blockDim.x + threadIdx.x;
    if (i < N_NODES) { g_ssrc[i] = 0.f; g_sdst[i] = 0.f; }   // clear for layer 1
    if (i >= M * 128) return;
    int row = i >> 7;
    int c2  = (i & 127) * 2;
    float2 v = *(const float2*)(A + (size_t)row * 256 + c2);
    __nv_bfloat16 h0 = __float2bfloat16_rn(v.x);
    __nv_bfloat16 h1 = __float2bfloat16_rn(v.y);
    __nv_bfloat162 hi; hi.x = h0; hi.y = h1;
    __nv_bfloat162 lo;
    lo.x = __float2bfloat16_rn(v.x - __bfloat162float(h0));
    lo.y = __float2bfloat16_rn(v.y - __bfloat162float(h1));
    __nv_bfloat16* r = out + (size_t)row * KT + c2;
    *reinterpret_cast<__nv_bfloat162*>(r)       = hi;
    *reinterpret_cast<__nv_bfloat162*>(r + 256) = hi;
    *reinterpret_cast<__nv_bfloat162*>(r + 512) = lo;
}

// square weights -> bf16 split, n-major [hi | lo | hi], into g_wexp slots
__global__ void convert_w_all(const float* __restrict__ W1, const float* __restrict__ W2,
                              const float* __restrict__ W3, const float* __restrict__ Wp) {
    int i = blockIdx.x * blockDim.x + threadIdx.x;
    if (i >= 4 * 65536) return;
    int m = i >> 16, r = i & 65535;
    const float* W = (m == 0) ? W1 : (m == 1) ? W2 : (m == 2) ? W3 : Wp;
    int k = r >> 8;
    int n = r & 255;
    float v = W[r];
    size_t base = (size_t)m * WSLOT + (size_t)n * KT;
    __nv_bfloat16 h = __float2bfloat16_rn(v);
    __nv_bfloat16 l = __float2bfloat16_rn(v - __bfloat162float(h));
    g_wexp[base + k]       = h;
    g_wexp[base + 256 + k] = l;
    g_wexp[base + 512 + k] = h;
}

// ---------------- bf16 tensor-core GEMM (ldmatrix + 3-stage pipeline) --------
__device__ __forceinline__ uint32_t smem_u32(const void* p) {
    uint32_t a;
    asm("{ .reg .u64 t; cvta.to.shared.u64 t, %1; cvt.u32.u64 %0, t; }"
        : "=r"(a) : "l"(p));
    return a;
}

__device__ __forceinline__ void cp16(void* dst, const void* src, int sz) {
    unsigned d = (unsigned)__cvta_generic_to_shared(dst);
    asm volatile("cp.async.cg.shared.global [%0], [%1], 16, %2;\n"
                 :: "r"(d), "l"(src), "r"(sz));
}
#define CP_COMMIT() asm volatile("cp.async.commit_group;\n" ::: "memory")
#define CP_WAIT(n)  asm volatile("cp.async.wait_group %0;\n" :: "n"(n) : "memory")

#define LDSM_X4(r0, r1, r2, r3, addr) \
    asm volatile("ldmatrix.sync.aligned.m8n8.x4.shared.b16 {%0,%1,%2,%3}, [%4];" \
                 : "=r"(r0), "=r"(r1), "=r"(r2), "=r"(r3) : "r"(addr))

__device__ __forceinline__ void mma16816(float* c, const uint32_t* a, const uint32_t* b) {
    asm volatile(
        "mma.sync.aligned.m16n8k16.row.col.f32.bf16.bf16.f32 "
        "{%0,%1,%2,%3}, {%4,%5,%6,%7}, {%8,%9}, {%0,%1,%2,%3};\n"
        : "+f"(c[0]), "+f"(c[1]), "+f"(c[2]), "+f"(c[3])
        : "r"(a[0]), "r"(a[1]), "r"(a[2]), "r"(a[3]), "r"(b[0]), "r"(b[1]));
}

// C[M,Ncols] = A'[M,768] @ W'T[Ncols,768]^T, fp32 out.
// SCORES: atomicAdd row dots with a_src/a_dst.
template <bool BIAS, bool RELU, bool SCORES>
__global__ __launch_bounds__(256)
void gemm_bf16(const __nv_bfloat16* __restrict__ A,
               const __nv_bfloat16* __restrict__ BT,
               const float* __restrict__ bias,
               float* __restrict__ Cf,
               const float* __restrict__ a_src,
               const float* __restrict__ a_dst,
               int M, int Ncols) {
    constexpr int BK = 32, PITCH = 40;           // 80B row pitch, LDSM conflict-free
    constexpr int STAGE = 2 * 128 * PITCH;       // bf16 elems per stage (A+B)
    constexpr int STAGE_BYTES = STAGE * 2;       // 20480
    extern __shared__ __align__(16) unsigned char smraw[];
    __nv_bfloat16* sm = reinterpret_cast<__nv_bfloat16*>(smraw);

    int tid = threadIdx.x, lane = tid & 31, wid = tid >> 5;
    int brow = blockIdx.x * 128, bcol = blockIdx.y * 128;
    int wm = (wid & 3) * 32, wn = (wid >> 2) * 64;
    int g = lane >> 2, tq = lane & 3;

    float c[2][8][4];
    #pragma unroll
    for (int i = 0; i < 2; i++)
        #pragma unroll
        for (int j = 0; j < 8; j++)
            #pragma unroll
            for (int q = 0; q < 4; q++) c[i][j][q] = 0.f;

    int lrow = tid >> 1;
    int lck  = (tid & 1) * 16;

    auto loadStage = [&](int st, int k0) {
        __nv_bfloat16* sA = sm + st * STAGE;
        __nv_bfloat16* sB = sA + 128 * PITCH;
        {
            bool ok = (brow + lrow) < M;
            const __nv_bfloat16* ga = A + (size_t)(brow + lrow) * KT + k0 + lck;
            int sz = ok ? 16 : 0;
            cp16(&sA[lrow * PITCH + lck],     ok ? (const void*)ga       : (const void*)A, sz);
            cp16(&sA[lrow * PITCH + lck + 8], ok ? (const void*)(ga + 8) : (const void*)A, sz);
        }
        {
            bool ok = (bcol + lrow) < Ncols;
            const __nv_bfloat16* gb = BT + (size_t)(bcol + lrow) * KT + k0 + lck;
            int sz = ok ? 16 : 0;
            cp16(&sB[lrow * PITCH + lck],     ok ? (const void*)gb       : (const void*)BT, sz);
            cp16(&sB[lrow * PITCH + lck + 8], ok ? (const void*)(gb + 8) : (const void*)BT, sz);
        }
    };

    loadStage(0, 0);  CP_COMMIT();
    loadStage(1, BK); CP_COMMIT();

    // ldmatrix per-lane address offsets (bytes within a stage)
    uint32_t smB  = smem_u32(sm);
    uint32_t aOff = (uint32_t)((wm + (lane & 7) + ((lane >> 3) & 1) * 8) * 80)
                    + (uint32_t)(lane >> 4) * 16;
    uint32_t bOff = 10240u
                    + (uint32_t)((wn + (lane & 7) + (lane >> 4) * 8) * 80)
                    + (uint32_t)((lane >> 3) & 1) * 16;

    const int numK = KT / BK;   // 24
    for (int it = 0; it < numK; ++it) {
        CP_WAIT(1);
        __syncthreads();
        if (it + 2 < numK) loadStage((it + 2) % 3, (it + 2) * BK);
        CP_COMMIT();

        uint32_t stBase = smB + (uint32_t)((it % 3) * STAGE_BYTES);
        uint32_t aA = stBase + aOff;
        uint32_t bA = stBase + bOff;

        #pragma unroll
        for (int kk = 0; kk < 2; ++kk) {
            uint32_t ko = kk * 32;   // 16 bf16 = 32 bytes
            uint32_t a[2][4], b[8][2];
            #pragma unroll
            for (int i = 0; i < 2; i++)
                LDSM_X4(a[i][0], a[i][1], a[i][2], a[i][3], aA + i * 1280 + ko);
            #pragma unroll
            for (int jp = 0; jp < 4; jp++) {
                uint32_t r0, r1, r2, r3;
                LDSM_X4(r0, r1, r2, r3, bA + jp * 1280 + ko);
                b[2 * jp][0]     = r0; b[2 * jp][1]     = r1;
                b[2 * jp + 1][0] = r2; b[2 * jp + 1][1] = r3;
            }
            #pragma unroll
            for (int i = 0; i < 2; i++)
                #pragma unroll
                for (int j = 0; j < 8; j++) mma16816(c[i][j], a[i], b[j]);
        }
    }

    // ---- epilogue ----
    float asv[8][2], adv[8][2];
    if (SCORES) {
        #pragma unroll
        for (int j = 0; j < 8; j++) {
            int gc = bcol + wn + 8 * j + 2 * tq;
            asv[j][0] = a_src[gc]; asv[j][1] = a_src[gc + 1];
            adv[j][0] = a_dst[gc]; adv[j][1] = a_dst[gc + 1];
        }
    }
    #pragma unroll
    for (int i = 0; i < 2; i++) {
        #pragma unroll
        for (int half = 0; half < 2; half++) {
            int gr = brow + wm + 16 * i + 8 * half + g;
            bool ok = gr < M;
            float ps = 0.f, pd = 0.f;
            #pragma unroll
            for (int j = 0; j < 8; j++) {
                int gc = bcol + wn + 8 * j + 2 * tq;
                float v0 = c[i][j][half * 2 + 0];
                float v1 = c[i][j][half * 2 + 1];
                if (BIAS) { v0 += bias[gc]; v1 += bias[gc + 1]; }
                if (RELU) { v0 = fmaxf(v0, 0.f); v1 = fmaxf(v1, 0.f); }
                if (SCORES) {
                    ps += v0 * asv[j][0] + v1 * asv[j][1];
                    pd += v0 * adv[j][0] + v1 * adv[j][1];
                }
                if (ok) {
                    *reinterpret_cast<float2*>(Cf + (size_t)gr * Ncols + gc) =
                        make_float2(v0, v1);
                }
            }
            if (SCORES) {
                ps += __shfl_xor_sync(FULL_MASK, ps, 1);
                ps += __shfl_xor_sync(FULL_MASK, ps, 2);
                pd += __shfl_xor_sync(FULL_MASK, pd, 1);
                pd += __shfl_xor_sync(FULL_MASK, pd, 2);
                if (tq == 0 && ok) {
                    atomicAdd(&g_ssrc[gr], ps);
                    atomicAdd(&g_sdst[gr], pd);
                }
            }
        }
    }
}

// ---------------- fp32 readout: out[M,40] = h[M,256] @ Wr + br ----------------
#define RO_ROWS 32
#define RO_THREADS 320
__global__ __launch_bounds__(RO_THREADS)
void readout_kernel(const float* __restrict__ h, const float* __restrict__ Wr,
                    const float* __restrict__ br, float* __restrict__ out, int M) {
    extern __shared__ __align__(16) unsigned char roraw[];
    float* sW = reinterpret_cast<float*>(roraw);                 // [256*40]
    float* sH = sW + 256 * 40;                                   // [32][260]
    int t = threadIdx.x;
    int R0 = blockIdx.x * RO_ROWS;

    for (int i = t; i < 256 * 40 / 4; i += RO_THREADS)
        reinterpret_cast<float4*>(sW)[i] = reinterpret_cast<const float4*>(Wr)[i];
    for (int i = t; i < RO_ROWS * 64; i += RO_THREADS) {
        int r = i >> 6, k4 = i & 63;
        float4 v = make_float4(0.f, 0.f, 0.f, 0.f);
        if (R0 + r < M)
            v = *reinterpret_cast<const float4*>(h + (size_t)(R0 + r) * 256 + k4 * 4);
        *reinterpret_cast<float4*>(&sH[r * 260 + k4 * 4]) = v;
    }
    __syncthreads();

    int r = t / 10, cg = t % 10;       // 32 rows x 10 groups of 4 cols
    float4 acc = *reinterpret_cast<const float4*>(br + cg * 4);
    const float* hr = &sH[r * 260];
    #pragma unroll 8
    for (int k = 0; k < 256; k++) {
        float hv = hr[k];
        float4 w = *reinterpret_cast<const float4*>(&sW[k * 40 + cg * 4]);
        acc.x += hv * w.x; acc.y += hv * w.y;
        acc.z += hv * w.z; acc.w += hv * w.w;
    }
    if (R0 + r < M)
        *reinterpret_cast<float4*>(out + (size_t)(R0 + r) * 40 + cg * 4) = acc;
}

// ---------------- GAT aggregation: one warp per dst; emits bf16 split --------
template <bool RELU>
__global__ void aggregate_kernel(const float* __restrict__ h,
                                 const float* __restrict__ bias,
                                 __nv_bfloat16* __restrict__ outExp) {
    int d    = (blockIdx.x * blockDim.x + threadIdx.x) >> 5;
    int lane = threadIdx.x & 31;
    if (d >= N_NODES) return;
    int start = g_offs[d];
    int end   = g_offs[d + 1];
    float sd  = g_sdst[d];

    float m = -1e30f;
    for (int i = start + lane; i < end; i += 32) {
        float sc = g_ssrc[g_csr[i]] + sd;
        sc = sc > 0.f ? sc : 0.2f * sc;
        m = fmaxf(m, sc);
    }
    #pragma unroll
    for (int o = 16; o > 0; o >>= 1) m = fmaxf(m, __shfl_xor_sync(FULL_MASK, m, o));

    float acc[8] = {0.f, 0.f, 0.f, 0.f, 0.f, 0.f, 0.f, 0.f};
    float denom = 0.f;
    for (int base = start; base < end; base += 32) {
        int i = base + lane;
        float w = 0.f;
        int s = 0;
        if (i < end) {
            s = g_csr[i];
            float sc = g_ssrc[s] + sd;
            sc = sc > 0.f ? sc : 0.2f * sc;
            w = __expf(sc - m);
        }
        denom += w;
        int cnt = min(32, end - base);
        int j = 0;
        for (; j + 1 < cnt; j += 2) {
            float w0 = __shfl_sync(FULL_MASK, w, j);
            int   s0 = __shfl_sync(FULL_MASK, s, j);
            float w1 = __shfl_sync(FULL_MASK, w, j + 1);
            int   s1 = __shfl_sync(FULL_MASK, s, j + 1);
            const float4* p0 = reinterpret_cast<const float4*>(h + (size_t)s0 * HID);
            const float4* p1 = reinterpret_cast<const float4*>(h + (size_t)s1 * HID);
            float4 a0 = p0[lane * 2],     b0 = p1[lane * 2];
            float4 a1 = p0[lane * 2 + 1], b1 = p1[lane * 2 + 1];
            acc[0] += w0 * a0.x + w1 * b0.x; acc[1] += w0 * a0.y + w1 * b0.y;
            acc[2] += w0 * a0.z + w1 * b0.z; acc[3] += w0 * a0.w + w1 * b0.w;
            acc[4] += w0 * a1.x + w1 * b1.x; acc[5] += w0 * a1.y + w1 * b1.y;
            acc[6] += w0 * a1.z + w1 * b1.z; acc[7] += w0 * a1.w + w1 * b1.w;
        }
        if (j < cnt) {
            float w0 = __shfl_sync(FULL_MASK, w, j);
            int   s0 = __shfl_sync(FULL_MASK, s, j);
            const float4* p0 = reinterpret_cast<const float4*>(h + (size_t)s0 * HID);
            float4 a0 = p0[lane * 2];
            float4 a1 = p0[lane * 2 + 1];
            acc[0] += w0 * a0.x; acc[1] += w0 * a0.y;
            acc[2] += w0 * a0.z; acc[3] += w0 * a0.w;
            acc[4] += w0 * a1.x; acc[5] += w0 * a1.y;
            acc[6] += w0 * a1.z; acc[7] += w0 * a1.w;
        }
    }
    #pragma unroll
    for (int o = 16; o > 0; o >>= 1) denom += __shfl_xor_sync(FULL_MASK, denom, o);
    float inv = 1.f / (denom + 1e-16f);

    const float* bp = bias + lane * 8;
    __nv_bfloat16* op = outExp + (size_t)d * KT + lane * 8;
    #pragma unroll
    for (int k = 0; k < 8; k += 2) {
        float v0 = acc[k] * inv + bp[k];
        float v1 = acc[k + 1] * inv + bp[k + 1];
        if (RELU) { v0 = fmaxf(v0, 0.f); v1 = fmaxf(v1, 0.f); }
        __nv_bfloat16 h0 = __float2bfloat16_rn(v0);
        __nv_bfloat16 h1 = __float2bfloat16_rn(v1);
        __nv_bfloat162 hi; hi.x = h0; hi.y = h1;
        __nv_bfloat162 lo;
        lo.x = __float2bfloat16_rn(v0 - __bfloat162float(h0));
        lo.y = __float2bfloat16_rn(v1 - __bfloat162float(h1));
        *reinterpret_cast<__nv_bfloat162*>(op + k)       = hi;
        *reinterpret_cast<__nv_bfloat162*>(op + 256 + k) = hi;
        *reinterpret_cast<__nv_bfloat162*>(op + 512 + k) = lo;
    }
}

// ---------------- launch ------------------------------------------------------
extern "C" void kernel_launch(void* const* d_in, const int* in_sizes, int n_in,
                              void* d_out, int out_size) {
    const float* x    = (const float*)d_in[0];
    const void*  edge = d_in[1];
    const float* as1 = (const float*)d_in[3];
    const float* ad1 = (const float*)d_in[4];
    const float* b1 = (const float*)d_in[5];
    const float* as2 = (const float*)d_in[7];
    const float* ad2 = (const float*)d_in[8];
    const float* b2 = (const float*)d_in[9];
    const float* as3 = (const float*)d_in[11];
    const float* ad3 = (const float*)d_in[12];
    const float* b3 = (const float*)d_in[13];
    const float* bp = (const float*)d_in[15];
    const float* Wr = (const float*)d_in[16];
    const float* br = (const float*)d_in[17];
    float* out = (float*)d_out;

    int E = in_sizes[1] / 2;

    float* h;
    __nv_bfloat16 *aexp, *wexp;
    cudaGetSymbolAddress((void**)&h,    g_h);
    cudaGetSymbolAddress((void**)&aexp, g_aexp);
    cudaGetSymbolAddress((void**)&wexp, g_wexp);

    const int TPB = 256;
    const int SMEM = 3 * 2 * 128 * 40 * 2;   // 61440 B (3-stage double tiles)
    const int ROSMEM = (256 * 40 + RO_ROWS * 260) * 4;   // 74240 B
    cudaFuncSetAttribute(gemm_bf16<false, false, true>,
                         cudaFuncAttributeMaxDynamicSharedMemorySize, SMEM);
    cudaFuncSetAttribute(gemm_bf16<true, true, false>,
                         cudaFuncAttributeMaxDynamicSharedMemorySize, SMEM);
    cudaFuncSetAttribute(readout_kernel,
                         cudaFuncAttributeMaxDynamicSharedMemorySize, ROSMEM);

    int nodeBlocks = (N_NODES + TPB - 1) / TPB;
    int warpNodeBlocks = (N_NODES * 32 + TPB - 1) / TPB;
    int scanBlocks = (N_NODES + 1023) / 1024;

    dim3 gH((N_NODES + 127) / 128, 2);
    int roBlocks = (N_NODES + RO_ROWS - 1) / RO_ROWS;

    // init + converts (scores for layer 1 cleared inside convert_split)
    detect_and_init<<<nodeBlocks, TPB>>>(edge, E);
    convert_split_kernel<<<(N_NODES * 128 + TPB - 1) / TPB, TPB>>>(x, aexp, N_NODES);
    convert_w_all<<<(4 * 65536 + TPB - 1) / TPB, TPB>>>(
        (const float*)d_in[2], (const float*)d_in[6], (const float*)d_in[10],
        (const float*)d_in[14]);

    // GEMM layer 1 (fused scores)  <- ncu sampling slot
    gemm_bf16<false, false, true><<<gH, TPB, SMEM>>>(
        aexp, wexp, nullptr, h, as1, ad1, N_NODES, 256);

    // CSR build (independent of GEMM result)
    hist_kernel<<<(E + TPB - 1) / TPB, TPB>>>(edge, E);
    scan1_kernel<<<scanBlocks, 1024>>>();
    scan2_kernel<<<1, 64>>>(scanBlocks);
    scan3_kernel<<<nodeBlocks, TPB>>>();
    scatter_kernel<<<(E + N_NODES + TPB - 1) / TPB, TPB>>>(edge, E);

    // layer 1 aggregate
    aggregate_kernel<true><<<warpNodeBlocks, TPB>>>(h, b1, aexp);

    // layer 2
    clear_scores_kernel<<<nodeBlocks, TPB>>>();
    gemm_bf16<false, false, true><<<gH, TPB, SMEM>>>(
        aexp, wexp + WSLOT, nullptr, h, as2, ad2, N_NODES, 256);
    aggregate_kernel<true><<<warpNodeBlocks, TPB>>>(h, b2, aexp);

    // layer 3 (no relu)
    clear_scores_kernel<<<nodeBlocks, TPB>>>();
    gemm_bf16<false, false, true><<<gH, TPB, SMEM>>>(
        aexp, wexp + 2 * WSLOT, nullptr, h, as3, ad3, N_NODES, 256);
    aggregate_kernel<false><<<warpNodeBlocks, TPB>>>(h, b3, aexp);

    // post1: Linear + ReLU -> fp32 h (no split; readout consumes fp32)
    gemm_bf16<true, true, false><<<gH, TPB, SMEM>>>(
        aexp, wexp + 3 * WSLOT, bp, h, nullptr, nullptr, N_NODES, 256);

    // readout: exact fp32 h @ Wr + br
    readout_kernel<<<roBlocks, RO_THREADS, ROSMEM>>>(h, Wr, br, out, N_NODES);
}

// round 14
// speedup vs baseline: 1.0539x; 1.0539x over previous
#include <cuda_runtime.h>
#include <cuda_bf16.h>
#include <cstdint>

#define N_NODES 50000
#define HID 256
#define NCLS 40
#define E_MAX 1000000
#define KT 768                    // 3 * 256 split-K
#define FULL_MASK 0xFFFFFFFFu
#define WSLOT 196608              // 256*768 bf16 per weight slot

// ---------------- scratch (device globals; no allocations allowed) ----------
__device__ float          g_h[(size_t)N_NODES * HID];      // h = A' @ W' (fp32)
__device__ __nv_bfloat16  g_aexp[(size_t)N_NODES * KT];    // split A operand
__device__ __nv_bfloat16  g_aexp2[(size_t)N_NODES * KT];   // split A operand (post1 out)
__device__ __nv_bfloat16  g_wexp[4 * WSLOT + 40 * KT];     // all split weights, n-major
__device__ __align__(16) float g_ssrcp[(size_t)4 * N_NODES]; // 4 partials per node
__device__ __align__(16) float g_sdstp[(size_t)4 * N_NODES];
__device__ int   g_deg[N_NODES];                           // zero at rest (scan3 resets)
__device__ int   g_offs[N_NODES + 1];
__device__ int   g_cursor[N_NODES];
__device__ int   g_csr[E_MAX];
__device__ int   g_bsum[64];
__device__ int   g_bbase[64];
__device__ int   g_idx64;

// ---------------- edge index access (dtype-agnostic) ------------------------
__device__ __forceinline__ int edge_val(const void* e, long long i) {
    return g_idx64 ? (int)((const long long*)e)[i] : ((const int*)e)[i];
}

// ---------------- CSR construction ------------------------------------------
__global__ void detect_kernel(const void* edge, int E) {
    if (threadIdx.x == 0) {
        const long long* p = (const long long*)edge;
        int n = E < 1024 ? E : 1024;
        int ok = 1;
        for (int i = 0; i < n; i++) {
            long long v = p[i];
            if (v < 0 || v >= N_NODES) { ok = 0; break; }
        }
        g_idx64 = ok;
    }
}

__global__ void hist_kernel(const void* edge, int E) {
    int i = blockIdx.x * blockDim.x + threadIdx.x;
    if (i < E) atomicAdd(&g_deg[edge_val(edge, (long long)E + i)], 1);
}

__global__ void scan1_kernel() {
    __shared__ int sh[1024];
    int t = threadIdx.x;
    int i = blockIdx.x * 1024 + t;
    int v = (i < N_NODES) ? (g_deg[i] + 1) : 0;   // +1 = self-loop
    sh[t] = v;
    __syncthreads();
    #pragma unroll
    for (int off = 1; off < 1024; off <<= 1) {
        int add = (t >= off) ? sh[t - off] : 0;
        __syncthreads();
        sh[t] += add;
        __syncthreads();
    }
    if (i < N_NODES) g_offs[i] = sh[t] - v;
    if (t == 1023) g_bsum[blockIdx.x] = sh[1023];
}

__global__ void scan2_kernel(int nb) {
    __shared__ int sh[64];
    int t = threadIdx.x;
    int v = (t < nb) ? g_bsum[t] : 0;
    sh[t] = v;
    __syncthreads();
    #pragma unroll
    for (int off = 1; off < 64; off <<= 1) {
        int add = (t >= off) ? sh[t - off] : 0;
        __syncthreads();
        sh[t] += add;
        __syncthreads();
    }
    g_bbase[t] = sh[t] - v;
    if (t == nb - 1) g_offs[N_NODES] = sh[t];
}

__global__ void scan3_kernel() {
    int i = blockIdx.x * blockDim.x + threadIdx.x;
    if (i < N_NODES) {
        int o = g_offs[i] + g_bbase[i >> 10];
        g_offs[i] = o;
        g_cursor[i] = o;
        g_deg[i] = 0;   // reset for next launch (deterministic across replays)
    }
}

__global__ void scatter_kernel(const void* edge, int E) {
    int i = blockIdx.x * blockDim.x + threadIdx.x;
    if (i < E) {
        int s = edge_val(edge, i);
        int d = edge_val(edge, (long long)E + i);
        g_csr[atomicAdd(&g_cursor[d], 1)] = s;
    } else if (i < E + N_NODES) {
        int v = i - E;
        g_csr[atomicAdd(&g_cursor[v], 1)] = v;
    }
}

// ---------------- split conversions ------------------------------------------
// A' row layout: [hi(256) | hi(256) | lo(256)]
__global__ void convert_split_kernel(const float* __restrict__ A,
                                     __nv_bfloat16* __restrict__ out, int M) {
    int i = blockIdx.x * blockDim.x + threadIdx.x;
    if (i >= M * 128) return;
    int row = i >> 7;
    int c2  = (i & 127) * 2;
    float2 v = *(const float2*)(A + (size_t)row * 256 + c2);
    __nv_bfloat16 h0 = __float2bfloat16_rn(v.x);
    __nv_bfloat16 h1 = __float2bfloat16_rn(v.y);
    __nv_bfloat162 hi; hi.x = h0; hi.y = h1;
    __nv_bfloat162 lo;
    lo.x = __float2bfloat16_rn(v.x - __bfloat162float(h0));
    lo.y = __float2bfloat16_rn(v.y - __bfloat162float(h1));
    __nv_bfloat16* r = out + (size_t)row * KT + c2;
    *reinterpret_cast<__nv_bfloat162*>(r)       = hi;
    *reinterpret_cast<__nv_bfloat162*>(r + 256) = hi;
    *reinterpret_cast<__nv_bfloat162*>(r + 512) = lo;
}

// all weights -> bf16 split, n-major [hi | lo | hi], into g_wexp slots
__global__ void convert_w_all(const float* __restrict__ W1, const float* __restrict__ W2,
                              const float* __restrict__ W3, const float* __restrict__ Wp,
                              const float* __restrict__ Wr) {
    int i = blockIdx.x * blockDim.x + threadIdx.x;
    const int SQ = 4 * 65536;
    float v; size_t base; int k;
    if (i < SQ) {
        int m = i >> 16, r = i & 65535;
        const float* W = (m == 0) ? W1 : (m == 1) ? W2 : (m == 2) ? W3 : Wp;
        k = r >> 8;
        int n = r & 255;
        v = W[r];
        base = (size_t)m * WSLOT + (size_t)n * KT;
    } else if (i < SQ + 256 * 40) {
        int r = i - SQ;
        k = r / 40;
        int n = r % 40;
        v = Wr[r];
        base = (size_t)4 * WSLOT + (size_t)n * KT;
    } else return;
    __nv_bfloat16 h = __float2bfloat16_rn(v);
    __nv_bfloat16 l = __float2bfloat16_rn(v - __bfloat162float(h));
    g_wexp[base + k]       = h;
    g_wexp[base + 256 + k] = l;
    g_wexp[base + 512 + k] = h;
}

// ---------------- bf16 tensor-core GEMM (ldmatrix + 3-stage pipeline) --------
__device__ __forceinline__ uint32_t smem_u32(const void* p) {
    uint32_t a;
    asm("{ .reg .u64 t; cvta.to.shared.u64 t, %1; cvt.u32.u64 %0, t; }"
        : "=r"(a) : "l"(p));
    return a;
}

__device__ __forceinline__ void cp16(void* dst, const void* src, int sz) {
    unsigned d = (unsigned)__cvta_generic_to_shared(dst);
    asm volatile("cp.async.cg.shared.global [%0], [%1], 16, %2;\n"
                 :: "r"(d), "l"(src), "r"(sz));
}
#define CP_COMMIT() asm volatile("cp.async.commit_group;\n" ::: "memory")
#define CP_WAIT(n)  asm volatile("cp.async.wait_group %0;\n" :: "n"(n) : "memory")

#define LDSM_X4(r0, r1, r2, r3, addr) \
    asm volatile("ldmatrix.sync.aligned.m8n8.x4.shared.b16 {%0,%1,%2,%3}, [%4];" \
                 : "=r"(r0), "=r"(r1), "=r"(r2), "=r"(r3) : "r"(addr))

__device__ __forceinline__ void mma16816(float* c, const uint32_t* a, const uint32_t* b) {
    asm volatile(
        "mma.sync.aligned.m16n8k16.row.col.f32.bf16.bf16.f32 "
        "{%0,%1,%2,%3}, {%4,%5,%6,%7}, {%8,%9}, {%0,%1,%2,%3};\n"
        : "+f"(c[0]), "+f"(c[1]), "+f"(c[2]), "+f"(c[3])
        : "r"(a[0]), "r"(a[1]), "r"(a[2]), "r"(a[3]), "r"(b[0]), "r"(b[1]));
}

__device__ __forceinline__ void stcs32(void* p, uint32_t v) {
    asm volatile("st.global.cs.u32 [%0], %1;" :: "l"(p), "r"(v));
}

// C[M,Ncols] = A'[M,768] @ W'T[Ncols,768]^T.
// OUTMODE 0: fp32 out; 1: bf16 split out.
// SCORES: per-(y,wn-half) partial row dots stored to unique slots (no atomics).
template <int OUTMODE, bool BIAS, bool RELU, bool SCORES>
__global__ __launch_bounds__(256)
void gemm_bf16(const __nv_bfloat16* __restrict__ A,
               const __nv_bfloat16* __restrict__ BT,
               const float* __restrict__ bias,
               float* __restrict__ Cf,
               __nv_bfloat16* __restrict__ Cs,
               const float* __restrict__ a_src,
               const float* __restrict__ a_dst,
               int M, int Ncols) {
    constexpr int BK = 32, PITCH = 40;           // 80B row pitch, LDSM conflict-free
    constexpr int STAGE = 2 * 128 * PITCH;       // bf16 elems per stage (A+B)
    constexpr int STAGE_BYTES = STAGE * 2;       // 20480
    extern __shared__ __align__(16) unsigned char smraw[];
    __nv_bfloat16* sm = reinterpret_cast<__nv_bfloat16*>(smraw);

    int tid = threadIdx.x, lane = tid & 31, wid = tid >> 5;
    int brow = blockIdx.x * 128, bcol = blockIdx.y * 128;
    int wm = (wid & 3) * 32, wn = (wid >> 2) * 64;
    int g = lane >> 2, tq = lane & 3;

    float c[2][8][4];
    #pragma unroll
    for (int i = 0; i < 2; i++)
        #pragma unroll
        for (int j = 0; j < 8; j++)
            #pragma unroll
            for (int q = 0; q < 4; q++) c[i][j][q] = 0.f;

    int lrow = tid >> 1;
    int lck  = (tid & 1) * 16;

    auto loadStage = [&](int st, int k0) {
        __nv_bfloat16* sA = sm + st * STAGE;
        __nv_bfloat16* sB = sA + 128 * PITCH;
        {
            bool ok = (brow + lrow) < M;
            const __nv_bfloat16* ga = A + (size_t)(brow + lrow) * KT + k0 + lck;
            int sz = ok ? 16 : 0;
            cp16(&sA[lrow * PITCH + lck],     ok ? (const void*)ga       : (const void*)A, sz);
            cp16(&sA[lrow * PITCH + lck + 8], ok ? (const void*)(ga + 8) : (const void*)A, sz);
        }
        {
            bool ok = (bcol + lrow) < Ncols;
            const __nv_bfloat16* gb = BT + (size_t)(bcol + lrow) * KT + k0 + lck;
            int sz = ok ? 16 : 0;
            cp16(&sB[lrow * PITCH + lck],     ok ? (const void*)gb       : (const void*)BT, sz);
            cp16(&sB[lrow * PITCH + lck + 8], ok ? (const void*)(gb + 8) : (const void*)BT, sz);
        }
    };

    loadStage(0, 0);  CP_COMMIT();
    loadStage(1, BK); CP_COMMIT();

    // ldmatrix per-lane address offsets (bytes within a stage)
    uint32_t smB  = smem_u32(sm);
    uint32_t aOff = (uint32_t)((wm + (lane & 7) + ((lane >> 3) & 1) * 8) * 80)
                    + (uint32_t)(lane >> 4) * 16;
    uint32_t bOff = 10240u
                    + (uint32_t)((wn + (lane & 7) + (lane >> 4) * 8) * 80)
                    + (uint32_t)((lane >> 3) & 1) * 16;

    const int numK = KT / BK;   // 24
    for (int it = 0; it < numK; ++it) {
        CP_WAIT(1);
        __syncthreads();
        if (it + 2 < numK) loadStage((it + 2) % 3, (it + 2) * BK);
        CP_COMMIT();

        uint32_t stBase = smB + (uint32_t)((it % 3) * STAGE_BYTES);
        uint32_t aA = stBase + aOff;
        uint32_t bA = stBase + bOff;

        #pragma unroll
        for (int kk = 0; kk < 2; ++kk) {
            uint32_t ko = kk * 32;   // 16 bf16 = 32 bytes
            uint32_t a[2][4], b[8][2];
            #pragma unroll
            for (int i = 0; i < 2; i++)
                LDSM_X4(a[i][0], a[i][1], a[i][2], a[i][3], aA + i * 1280 + ko);
            #pragma unroll
            for (int jp = 0; jp < 4; jp++) {
                uint32_t r0, r1, r2, r3;
                LDSM_X4(r0, r1, r2, r3, bA + jp * 1280 + ko);
                b[2 * jp][0]     = r0; b[2 * jp][1]     = r1;
                b[2 * jp + 1][0] = r2; b[2 * jp + 1][1] = r3;
            }
            #pragma unroll
            for (int i = 0; i < 2; i++)
                #pragma unroll
                for (int j = 0; j < 8; j++) mma16816(c[i][j], a[i], b[j]);
        }
    }

    // ---- epilogue ----
    float asv[8][2], adv[8][2];
    if (SCORES) {
        #pragma unroll
        for (int j = 0; j < 8; j++) {
            int gc = bcol + wn + 8 * j + 2 * tq;
            asv[j][0] = a_src[gc]; asv[j][1] = a_src[gc + 1];
            adv[j][0] = a_dst[gc]; adv[j][1] = a_dst[gc + 1];
        }
    }
    int slot = blockIdx.y * 2 + (wid >> 2);   // unique writer per (slot, row)
    #pragma unroll
    for (int i = 0; i < 2; i++) {
        #pragma unroll
        for (int half = 0; half < 2; half++) {
            int gr = brow + wm + 16 * i + 8 * half + g;
            bool ok = gr < M;
            float ps = 0.f, pd = 0.f;
            #pragma unroll
            for (int j = 0; j < 8; j++) {
                int gc = bcol + wn + 8 * j + 2 * tq;
                float v0 = c[i][j][half * 2 + 0];
                float v1 = c[i][j][half * 2 + 1];
                if (BIAS) { v0 += bias[gc]; v1 += (gc + 1 < Ncols) ? bias[gc + 1] : 0.f; }
                if (RELU) { v0 = fmaxf(v0, 0.f); v1 = fmaxf(v1, 0.f); }
                if (SCORES) {
                    ps += v0 * asv[j][0] + v1 * asv[j][1];
                    pd += v0 * adv[j][0] + v1 * adv[j][1];
                }
                if (ok) {
                    if (OUTMODE == 0) {
                        if (gc + 1 < Ncols) {
                            *reinterpret_cast<float2*>(Cf + (size_t)gr * Ncols + gc) =
                                make_float2(v0, v1);
                        } else if (gc < Ncols) {
                            Cf[(size_t)gr * Ncols + gc] = v0;
                        }
                    } else {
                        __nv_bfloat16 h0 = __float2bfloat16_rn(v0);
                        __nv_bfloat16 h1 = __float2bfloat16_rn(v1);
                        __nv_bfloat162 hi; hi.x = h0; hi.y = h1;
                        __nv_bfloat162 lo;
                        lo.x = __float2bfloat16_rn(v0 - __bfloat162float(h0));
                        lo.y = __float2bfloat16_rn(v1 - __bfloat162float(h1));
                        __nv_bfloat16* r = Cs + (size_t)gr * KT + gc;
                        *reinterpret_cast<__nv_bfloat162*>(r)       = hi;
                        *reinterpret_cast<__nv_bfloat162*>(r + 256) = hi;
                        *reinterpret_cast<__nv_bfloat162*>(r + 512) = lo;
                    }
                }
            }
            if (SCORES) {
                ps += __shfl_xor_sync(FULL_MASK, ps, 1);
                ps += __shfl_xor_sync(FULL_MASK, ps, 2);
                pd += __shfl_xor_sync(FULL_MASK, pd, 1);
                pd += __shfl_xor_sync(FULL_MASK, pd, 2);
                if (tq == 0 && ok) {
                    g_ssrcp[(size_t)gr * 4 + slot] = ps;
                    g_sdstp[(size_t)gr * 4 + slot] = pd;
                }
            }
        }
    }
}

// ---------------- GAT aggregation: one warp per dst; emits bf16 split --------
__device__ __forceinline__ float sum4(const float* p) {
    float4 v = *reinterpret_cast<const float4*>(p);
    return (v.x + v.y) + (v.z + v.w);
}

template <bool RELU>
__global__ void aggregate_kernel(const float* __restrict__ h,
                                 const float* __restrict__ bias,
                                 __nv_bfloat16* __restrict__ outExp) {
    int d    = (blockIdx.x * blockDim.x + threadIdx.x) >> 5;
    int lane = threadIdx.x & 31;
    if (d >= N_NODES) return;
    int start = g_offs[d];
    int end   = g_offs[d + 1];
    float sd  = sum4(&g_sdstp[(size_t)d * 4]);

    float m = -1e30f;
    for (int i = start + lane; i < end; i += 32) {
        int s = g_csr[i];
        float sc = sum4(&g_ssrcp[(size_t)s * 4]) + sd;
        sc = sc > 0.f ? sc : 0.2f * sc;
        m = fmaxf(m, sc);
    }
    #pragma unroll
    for (int o = 16; o > 0; o >>= 1) m = fmaxf(m, __shfl_xor_sync(FULL_MASK, m, o));

    float acc[8] = {0.f, 0.f, 0.f, 0.f, 0.f, 0.f, 0.f, 0.f};
    float denom = 0.f;
    for (int base = start; base < end; base += 32) {
        int i = base + lane;
        float w = 0.f;
        int s = 0;
        if (i < end) {
            s = g_csr[i];
            float sc = sum4(&g_ssrcp[(size_t)s * 4]) + sd;
            sc = sc > 0.f ? sc : 0.2f * sc;
            w = __expf(sc - m);
        }
        denom += w;
        int cnt = min(32, end - base);
        int j = 0;
        for (; j + 1 < cnt; j += 2) {
            float w0 = __shfl_sync(FULL_MASK, w, j);
            int   s0 = __shfl_sync(FULL_MASK, s, j);
            float w1 = __shfl_sync(FULL_MASK, w, j + 1);
            int   s1 = __shfl_sync(FULL_MASK, s, j + 1);
            const float4* p0 = reinterpret_cast<const float4*>(h + (size_t)s0 * HID);
            const float4* p1 = reinterpret_cast<const float4*>(h + (size_t)s1 * HID);
            float4 a0 = p0[lane * 2],     b0 = p1[lane * 2];
            float4 a1 = p0[lane * 2 + 1], b1 = p1[lane * 2 + 1];
            acc[0] += w0 * a0.x + w1 * b0.x; acc[1] += w0 * a0.y + w1 * b0.y;
            acc[2] += w0 * a0.z + w1 * b0.z; acc[3] += w0 * a0.w + w1 * b0.w;
            acc[4] += w0 * a1.x + w1 * b1.x; acc[5] += w0 * a1.y + w1 * b1.y;
            acc[6] += w0 * a1.z + w1 * b1.z; acc[7] += w0 * a1.w + w1 * b1.w;
        }
        if (j < cnt) {
            float w0 = __shfl_sync(FULL_MASK, w, j);
            int   s0 = __shfl_sync(FULL_MASK, s, j);
            const float4* p0 = reinterpret_cast<const float4*>(h + (size_t)s0 * HID);
            float4 a0 = p0[lane * 2];
            float4 a1 = p0[lane * 2 + 1];
            acc[0] += w0 * a0.x; acc[1] += w0 * a0.y;
            acc[2] += w0 * a0.z; acc[3] += w0 * a0.w;
            acc[4] += w0 * a1.x; acc[5] += w0 * a1.y;
            acc[6] += w0 * a1.z; acc[7] += w0 * a1.w;
        }
    }
    #pragma unroll
    for (int o = 16; o > 0; o >>= 1) denom += __shfl_xor_sync(FULL_MASK, denom, o);
    float inv = 1.f / (denom + 1e-16f);

    const float* bp = bias + lane * 8;
    __nv_bfloat16* op = outExp + (size_t)d * KT + lane * 8;
    #pragma unroll
    for (int k = 0; k < 8; k += 2) {
        float v0 = acc[k] * inv + bp[k];
        float v1 = acc[k + 1] * inv + bp[k + 1];
        if (RELU) { v0 = fmaxf(v0, 0.f); v1 = fmaxf(v1, 0.f); }
        __nv_bfloat16 h0 = __float2bfloat16_rn(v0);
        __nv_bfloat16 h1 = __float2bfloat16_rn(v1);
        __nv_bfloat162 hi; hi.x = h0; hi.y = h1;
        __nv_bfloat162 lo;
        lo.x = __float2bfloat16_rn(v0 - __bfloat162float(h0));
        lo.y = __float2bfloat16_rn(v1 - __bfloat162float(h1));
        // streaming stores: keep the h gather L2-resident (output is read-once later)
        stcs32(op + k,       *reinterpret_cast<uint32_t*>(&hi));
        stcs32(op + 256 + k, *reinterpret_cast<uint32_t*>(&hi));
        stcs32(op + 512 + k, *reinterpret_cast<uint32_t*>(&lo));
    }
}

// ---------------- launch ------------------------------------------------------
extern "C" void kernel_launch(void* const* d_in, const int* in_sizes, int n_in,
                              void* d_out, int out_size) {
    const float* x    = (const float*)d_in[0];
    const void*  edge = d_in[1];
    const float* as1 = (const float*)d_in[3];
    const float* ad1 = (const float*)d_in[4];
    const float* b1 = (const float*)d_in[5];
    const float* as2 = (const float*)d_in[7];
    const float* ad2 = (const float*)d_in[8];
    const float* b2 = (const float*)d_in[9];
    const float* as3 = (const float*)d_in[11];
    const float* ad3 = (const float*)d_in[12];
    const float* b3 = (const float*)d_in[13];
    const float* bp = (const float*)d_in[15];
    const float* br = (const float*)d_in[17];
    float* out = (float*)d_out;

    int E = in_sizes[1] / 2;

    float* h;
    __nv_bfloat16 *aexp, *aexp2, *wexp;
    cudaGetSymbolAddress((void**)&h,     g_h);
    cudaGetSymbolAddress((void**)&aexp,  g_aexp);
    cudaGetSymbolAddress((void**)&aexp2, g_aexp2);
    cudaGetSymbolAddress((void**)&wexp,  g_wexp);

    const int TPB = 256;
    const int SMEM = 3 * 2 * 128 * 40 * 2;   // 61440 B (3-stage double tiles)
    cudaFuncSetAttribute(gemm_bf16<0, false, false, true>,
                         cudaFuncAttributeMaxDynamicSharedMemorySize, SMEM);
    cudaFuncSetAttribute(gemm_bf16<1, true, true, false>,
                         cudaFuncAttributeMaxDynamicSharedMemorySize, SMEM);
    cudaFuncSetAttribute(gemm_bf16<0, true, false, false>,
                         cudaFuncAttributeMaxDynamicSharedMemorySize, SMEM);

    int nodeBlocks = (N_NODES + TPB - 1) / TPB;
    int warpNodeBlocks = (N_NODES * 32 + TPB - 1) / TPB;
    int scanBlocks = (N_NODES + 1023) / 1024;

    dim3 gH((N_NODES + 127) / 128, 2);
    dim3 gR((N_NODES + 127) / 128, 1);

    // init + converts
    detect_kernel<<<1, 32>>>(edge, E);
    convert_split_kernel<<<(N_NODES * 128 + TPB - 1) / TPB, TPB>>>(x, aexp, N_NODES);
    convert_w_all<<<(4 * 65536 + 256 * 40 + TPB - 1) / TPB, TPB>>>(
        (const float*)d_in[2], (const float*)d_in[6], (const float*)d_in[10],
        (const float*)d_in[14], (const float*)d_in[16]);

    // GEMM layer 1 (fused scores, slot stores)  <- ncu sampling slot
    gemm_bf16<0, false, false, true><<<gH, TPB, SMEM>>>(
        aexp, wexp, nullptr, h, nullptr, as1, ad1, N_NODES, 256);

    // CSR build (independent of GEMM result; deg starts at rest-state zero)
    hist_kernel<<<(E + TPB - 1) / TPB, TPB>>>(edge, E);
    scan1_kernel<<<scanBlocks, 1024>>>();
    scan2_kernel<<<1, 64>>>(scanBlocks);
    scan3_kernel<<<nodeBlocks, TPB>>>();
    scatter_kernel<<<(E + N_NODES + TPB - 1) / TPB, TPB>>>(edge, E);

    // layer 1 aggregate
    aggregate_kernel<true><<<warpNodeBlocks, TPB>>>(h, b1, aexp);

    // layer 2
    gemm_bf16<0, false, false, true><<<gH, TPB, SMEM>>>(
        aexp, wexp + WSLOT, nullptr, h, nullptr, as2, ad2, N_NODES, 256);
    aggregate_kernel<true><<<warpNodeBlocks, TPB>>>(h, b2, aexp);

    // layer 3 (no relu)
    gemm_bf16<0, false, false, true><<<gH, TPB, SMEM>>>(
        aexp, wexp + 2 * WSLOT, nullptr, h, nullptr, as3, ad3, N_NODES, 256);
    aggregate_kernel<false><<<warpNodeBlocks, TPB>>>(h, b3, aexp);

    // post1: Linear + ReLU -> bf16 split
    gemm_bf16<1, true, true, false><<<gH, TPB, SMEM>>>(
        aexp, wexp + 3 * WSLOT, bp, nullptr, aexp2, nullptr, nullptr, N_NODES, 256);
    // readout
    gemm_bf16<0, true, false, false><<<gR, TPB, SMEM>>>(
        aexp2, wexp + 4 * WSLOT, br, out, nullptr, nullptr, nullptr, N_NODES, NCLS);
}

// round 15
// speedup vs baseline: 1.1330x; 1.0751x over previous
#include <cuda_runtime.h>
#include <cuda_bf16.h>
#include <cstdint>

#define N_NODES 50000
#define HID 256
#define NCLS 40
#define E_MAX 1000000
#define KT 768                    // 3 * 256 split-K
#define FULL_MASK 0xFFFFFFFFu
#define WSLOT 196608              // 256*768 bf16 per weight slot

// ---------------- scratch (device globals; no allocations allowed) ----------
__device__ float          g_h[(size_t)N_NODES * HID];      // h = A' @ W' (fp32)
__device__ __nv_bfloat16  g_aexp[(size_t)N_NODES * KT];    // split A operand
__device__ __nv_bfloat16  g_aexp2[(size_t)N_NODES * KT];   // split A operand (post1 out)
__device__ __nv_bfloat16  g_wexp[4 * WSLOT + 40 * KT];     // all split weights, n-major
__device__ __align__(16) float g_ssrcp[(size_t)4 * N_NODES]; // 4 partials per node
__device__ __align__(16) float g_sdstp[(size_t)4 * N_NODES];
__device__ int   g_deg[N_NODES];                           // zero at rest (scan3 resets)
__device__ int   g_offs[N_NODES + 1];
__device__ int   g_cursor[N_NODES];
__device__ int   g_csr[E_MAX];
__device__ int   g_bsum[64];
__device__ int   g_bbase[64];
__device__ int   g_idx64;

// ---------------- edge index access (dtype-agnostic) ------------------------
__device__ __forceinline__ int edge_val(const void* e, long long i) {
    return g_idx64 ? (int)((const long long*)e)[i] : ((const int*)e)[i];
}

// ---------------- CSR construction ------------------------------------------
__global__ void detect_kernel(const void* edge, int E) {
    if (threadIdx.x == 0) {
        const long long* p = (const long long*)edge;
        int n = E < 1024 ? E : 1024;
        int ok = 1;
        for (int i = 0; i < n; i++) {
            long long v = p[i];
            if (v < 0 || v >= N_NODES) { ok = 0; break; }
        }
        g_idx64 = ok;
    }
}

__global__ void hist_kernel(const void* edge, int E) {
    int i = blockIdx.x * blockDim.x + threadIdx.x;
    if (i < E) atomicAdd(&g_deg[edge_val(edge, (long long)E + i)], 1);
}

__global__ void scan1_kernel() {
    __shared__ int sh[1024];
    int t = threadIdx.x;
    int i = blockIdx.x * 1024 + t;
    int v = (i < N_NODES) ? (g_deg[i] + 1) : 0;   // +1 = self-loop
    sh[t] = v;
    __syncthreads();
    #pragma unroll
    for (int off = 1; off < 1024; off <<= 1) {
        int add = (t >= off) ? sh[t - off] : 0;
        __syncthreads();
        sh[t] += add;
        __syncthreads();
    }
    if (i < N_NODES) g_offs[i] = sh[t] - v;
    if (t == 1023) g_bsum[blockIdx.x] = sh[1023];
}

__global__ void scan2_kernel(int nb) {
    __shared__ int sh[64];
    int t = threadIdx.x;
    int v = (t < nb) ? g_bsum[t] : 0;
    sh[t] = v;
    __syncthreads();
    #pragma unroll
    for (int off = 1; off < 64; off <<= 1) {
        int add = (t >= off) ? sh[t - off] : 0;
        __syncthreads();
        sh[t] += add;
        __syncthreads();
    }
    g_bbase[t] = sh[t] - v;
    if (t == nb - 1) g_offs[N_NODES] = sh[t];
}

__global__ void scan3_kernel() {
    int i = blockIdx.x * blockDim.x + threadIdx.x;
    if (i < N_NODES) {
        int o = g_offs[i] + g_bbase[i >> 10];
        g_offs[i] = o;
        g_cursor[i] = o;
        g_deg[i] = 0;   // reset for next launch (deterministic across replays)
    }
}

__global__ void scatter_kernel(const void* edge, int E) {
    int i = blockIdx.x * blockDim.x + threadIdx.x;
    if (i < E) {
        int s = edge_val(edge, i);
        int d = edge_val(edge, (long long)E + i);
        g_csr[atomicAdd(&g_cursor[d], 1)] = s;
    } else if (i < E + N_NODES) {
        int v = i - E;
        g_csr[atomicAdd(&g_cursor[v], 1)] = v;
    }
}

// ---------------- split conversions ------------------------------------------
// A' row layout: [hi(256) | hi(256) | lo(256)]; 8 values/thread, 16B stores.
__global__ void convert_split_kernel(const float* __restrict__ A,
                                     __nv_bfloat16* __restrict__ out, int M) {
    int i = blockIdx.x * blockDim.x + threadIdx.x;
    if (i >= M * 32) return;
    int row = i >> 5;
    int c8  = (i & 31) * 8;
    const float4* src = reinterpret_cast<const float4*>(A + (size_t)row * 256 + c8);
    float4 v0 = src[0], v1 = src[1];
    float vals[8] = {v0.x, v0.y, v0.z, v0.w, v1.x, v1.y, v1.z, v1.w};
    __nv_bfloat16 hbuf[8], lbuf[8];
    #pragma unroll
    for (int k = 0; k < 8; k++) {
        hbuf[k] = __float2bfloat16_rn(vals[k]);
        lbuf[k] = __float2bfloat16_rn(vals[k] - __bfloat162float(hbuf[k]));
    }
    __nv_bfloat16* r = out + (size_t)row * KT + c8;
    *reinterpret_cast<uint4*>(r)       = *reinterpret_cast<uint4*>(hbuf);
    *reinterpret_cast<uint4*>(r + 256) = *reinterpret_cast<uint4*>(hbuf);
    *reinterpret_cast<uint4*>(r + 512) = *reinterpret_cast<uint4*>(lbuf);
}

// all weights -> bf16 split, n-major [hi | lo | hi], into g_wexp slots
__global__ void convert_w_all(const float* __restrict__ W1, const float* __restrict__ W2,
                              const float* __restrict__ W3, const float* __restrict__ Wp,
                              const float* __restrict__ Wr) {
    int i = blockIdx.x * blockDim.x + threadIdx.x;
    const int SQ = 4 * 65536;
    float v; size_t base; int k;
    if (i < SQ) {
        int m = i >> 16, r = i & 65535;
        const float* W = (m == 0) ? W1 : (m == 1) ? W2 : (m == 2) ? W3 : Wp;
        k = r >> 8;
        int n = r & 255;
        v = W[r];
        base = (size_t)m * WSLOT + (size_t)n * KT;
    } else if (i < SQ + 256 * 40) {
        int r = i - SQ;
        k = r / 40;
        int n = r % 40;
        v = Wr[r];
        base = (size_t)4 * WSLOT + (size_t)n * KT;
    } else return;
    __nv_bfloat16 h = __float2bfloat16_rn(v);
    __nv_bfloat16 l = __float2bfloat16_rn(v - __bfloat162float(h));
    g_wexp[base + k]       = h;
    g_wexp[base + 256 + k] = l;
    g_wexp[base + 512 + k] = h;
}

// ---------------- bf16 tensor-core GEMM (ldmatrix + 3-stage pipeline) --------
__device__ __forceinline__ uint32_t smem_u32(const void* p) {
    uint32_t a;
    asm("{ .reg .u64 t; cvta.to.shared.u64 t, %1; cvt.u32.u64 %0, t; }"
        : "=r"(a) : "l"(p));
    return a;
}

__device__ __forceinline__ void cp16(void* dst, const void* src, int sz) {
    unsigned d = (unsigned)__cvta_generic_to_shared(dst);
    asm volatile("cp.async.cg.shared.global [%0], [%1], 16, %2;\n"
                 :: "r"(d), "l"(src), "r"(sz));
}
#define CP_COMMIT() asm volatile("cp.async.commit_group;\n" ::: "memory")
#define CP_WAIT(n)  asm volatile("cp.async.wait_group %0;\n" :: "n"(n) : "memory")

#define LDSM_X4(r0, r1, r2, r3, addr) \
    asm volatile("ldmatrix.sync.aligned.m8n8.x4.shared.b16 {%0,%1,%2,%3}, [%4];" \
                 : "=r"(r0), "=r"(r1), "=r"(r2), "=r"(r3) : "r"(addr))

__device__ __forceinline__ void mma16816(float* c, const uint32_t* a, const uint32_t* b) {
    asm volatile(
        "mma.sync.aligned.m16n8k16.row.col.f32.bf16.bf16.f32 "
        "{%0,%1,%2,%3}, {%4,%5,%6,%7}, {%8,%9}, {%0,%1,%2,%3};\n"
        : "+f"(c[0]), "+f"(c[1]), "+f"(c[2]), "+f"(c[3])
        : "r"(a[0]), "r"(a[1]), "r"(a[2]), "r"(a[3]), "r"(b[0]), "r"(b[1]));
}

// C[M,Ncols] = A'[M,768] @ W'T[Ncols,768]^T.
// OUTMODE 0: fp32 out; 1: bf16 split out.
// SCORES: per-(y,wn-half) partial row dots stored to unique slots (no atomics).
template <int OUTMODE, bool BIAS, bool RELU, bool SCORES>
__global__ __launch_bounds__(256)
void gemm_bf16(const __nv_bfloat16* __restrict__ A,
               const __nv_bfloat16* __restrict__ BT,
               const float* __restrict__ bias,
               float* __restrict__ Cf,
               __nv_bfloat16* __restrict__ Cs,
               const float* __restrict__ a_src,
               const float* __restrict__ a_dst,
               int M, int Ncols) {
    constexpr int BK = 32, PITCH = 40;           // 80B row pitch, LDSM conflict-free
    constexpr int STAGE = 2 * 128 * PITCH;       // bf16 elems per stage (A+B)
    constexpr int STAGE_BYTES = STAGE * 2;       // 20480
    extern __shared__ __align__(16) unsigned char smraw[];
    __nv_bfloat16* sm = reinterpret_cast<__nv_bfloat16*>(smraw);

    int tid = threadIdx.x, lane = tid & 31, wid = tid >> 5;
    int brow = blockIdx.x * 128, bcol = blockIdx.y * 128;
    int wm = (wid & 3) * 32, wn = (wid >> 2) * 64;
    int g = lane >> 2, tq = lane & 3;

    float c[2][8][4];
    #pragma unroll
    for (int i = 0; i < 2; i++)
        #pragma unroll
        for (int j = 0; j < 8; j++)
            #pragma unroll
            for (int q = 0; q < 4; q++) c[i][j][q] = 0.f;

    int lrow = tid >> 1;
    int lck  = (tid & 1) * 16;

    auto loadStage = [&](int st, int k0) {
        __nv_bfloat16* sA = sm + st * STAGE;
        __nv_bfloat16* sB = sA + 128 * PITCH;
        {
            bool ok = (brow + lrow) < M;
            const __nv_bfloat16* ga = A + (size_t)(brow + lrow) * KT + k0 + lck;
            int sz = ok ? 16 : 0;
            cp16(&sA[lrow * PITCH + lck],     ok ? (const void*)ga       : (const void*)A, sz);
            cp16(&sA[lrow * PITCH + lck + 8], ok ? (const void*)(ga + 8) : (const void*)A, sz);
        }
        {
            bool ok = (bcol + lrow) < Ncols;
            const __nv_bfloat16* gb = BT + (size_t)(bcol + lrow) * KT + k0 + lck;
            int sz = ok ? 16 : 0;
            cp16(&sB[lrow * PITCH + lck],     ok ? (const void*)gb       : (const void*)BT, sz);
            cp16(&sB[lrow * PITCH + lck + 8], ok ? (const void*)(gb + 8) : (const void*)BT, sz);
        }
    };

    loadStage(0, 0);  CP_COMMIT();
    loadStage(1, BK); CP_COMMIT();

    // ldmatrix per-lane address offsets (bytes within a stage)
    uint32_t smB  = smem_u32(sm);
    uint32_t aOff = (uint32_t)((wm + (lane & 7) + ((lane >> 3) & 1) * 8) * 80)
                    + (uint32_t)(lane >> 4) * 16;
    uint32_t bOff = 10240u
                    + (uint32_t)((wn + (lane & 7) + (lane >> 4) * 8) * 80)
                    + (uint32_t)((lane >> 3) & 1) * 16;

    const int numK = KT / BK;   // 24
    for (int it = 0; it < numK; ++it) {
        CP_WAIT(1);
        __syncthreads();
        if (it + 2 < numK) loadStage((it + 2) % 3, (it + 2) * BK);
        CP_COMMIT();

        uint32_t stBase = smB + (uint32_t)((it % 3) * STAGE_BYTES);
        uint32_t aA = stBase + aOff;
        uint32_t bA = stBase + bOff;

        #pragma unroll
        for (int kk = 0; kk < 2; ++kk) {
            uint32_t ko = kk * 32;   // 16 bf16 = 32 bytes
            uint32_t a[2][4], b[8][2];
            #pragma unroll
            for (int i = 0; i < 2; i++)
                LDSM_X4(a[i][0], a[i][1], a[i][2], a[i][3], aA + i * 1280 + ko);
            #pragma unroll
            for (int jp = 0; jp < 4; jp++) {
                uint32_t r0, r1, r2, r3;
                LDSM_X4(r0, r1, r2, r3, bA + jp * 1280 + ko);
                b[2 * jp][0]     = r0; b[2 * jp][1]     = r1;
                b[2 * jp + 1][0] = r2; b[2 * jp + 1][1] = r3;
            }
            #pragma unroll
            for (int i = 0; i < 2; i++)
                #pragma unroll
                for (int j = 0; j < 8; j++) mma16816(c[i][j], a[i], b[j]);
        }
    }

    // ---- epilogue ----
    float asv[8][2], adv[8][2];
    if (SCORES) {
        #pragma unroll
        for (int j = 0; j < 8; j++) {
            int gc = bcol + wn + 8 * j + 2 * tq;
            asv[j][0] = a_src[gc]; asv[j][1] = a_src[gc + 1];
            adv[j][0] = a_dst[gc]; adv[j][1] = a_dst[gc + 1];
        }
    }
    int slot = blockIdx.y * 2 + (wid >> 2);   // unique writer per (slot, row)
    #pragma unroll
    for (int i = 0; i < 2; i++) {
        #pragma unroll
        for (int half = 0; half < 2; half++) {
            int gr = brow + wm + 16 * i + 8 * half + g;
            bool ok = gr < M;
            float ps = 0.f, pd = 0.f;
            #pragma unroll
            for (int j = 0; j < 8; j++) {
                int gc = bcol + wn + 8 * j + 2 * tq;
                float v0 = c[i][j][half * 2 + 0];
                float v1 = c[i][j][half * 2 + 1];
                if (BIAS) { v0 += bias[gc]; v1 += (gc + 1 < Ncols) ? bias[gc + 1] : 0.f; }
                if (RELU) { v0 = fmaxf(v0, 0.f); v1 = fmaxf(v1, 0.f); }
                if (SCORES) {
                    ps += v0 * asv[j][0] + v1 * asv[j][1];
                    pd += v0 * adv[j][0] + v1 * adv[j][1];
                }
                if (ok) {
                    if (OUTMODE == 0) {
                        if (gc + 1 < Ncols) {
                            *reinterpret_cast<float2*>(Cf + (size_t)gr * Ncols + gc) =
                                make_float2(v0, v1);
                        } else if (gc < Ncols) {
                            Cf[(size_t)gr * Ncols + gc] = v0;
                        }
                    } else {
                        __nv_bfloat16 h0 = __float2bfloat16_rn(v0);
                        __nv_bfloat16 h1 = __float2bfloat16_rn(v1);
                        __nv_bfloat162 hi; hi.x = h0; hi.y = h1;
                        __nv_bfloat162 lo;
                        lo.x = __float2bfloat16_rn(v0 - __bfloat162float(h0));
                        lo.y = __float2bfloat16_rn(v1 - __bfloat162float(h1));
                        __nv_bfloat16* r = Cs + (size_t)gr * KT + gc;
                        *reinterpret_cast<__nv_bfloat162*>(r)       = hi;
                        *reinterpret_cast<__nv_bfloat162*>(r + 256) = hi;
                        *reinterpret_cast<__nv_bfloat162*>(r + 512) = lo;
                    }
                }
            }
            if (SCORES) {
                ps += __shfl_xor_sync(FULL_MASK, ps, 1);
                ps += __shfl_xor_sync(FULL_MASK, ps, 2);
                pd += __shfl_xor_sync(FULL_MASK, pd, 1);
                pd += __shfl_xor_sync(FULL_MASK, pd, 2);
                if (tq == 0 && ok) {
                    g_ssrcp[(size_t)gr * 4 + slot] = ps;
                    g_sdstp[(size_t)gr * 4 + slot] = pd;
                }
            }
        }
    }
}

// ---------------- GAT aggregation: one warp per dst; emits bf16 split --------
__device__ __forceinline__ float sum4(const float* p) {
    float4 v = *reinterpret_cast<const float4*>(p);
    return (v.x + v.y) + (v.z + v.w);
}

template <bool RELU>
__global__ void aggregate_kernel(const float* __restrict__ h,
                                 const float* __restrict__ bias,
                                 __nv_bfloat16* __restrict__ outExp) {
    int d    = (blockIdx.x * blockDim.x + threadIdx.x) >> 5;
    int lane = threadIdx.x & 31;
    if (d >= N_NODES) return;
    int start = g_offs[d];
    int end   = g_offs[d + 1];
    float sd  = sum4(&g_sdstp[(size_t)d * 4]);

    float m = -1e30f;
    for (int i = start + lane; i < end; i += 32) {
        int s = g_csr[i];
        float sc = sum4(&g_ssrcp[(size_t)s * 4]) + sd;
        sc = sc > 0.f ? sc : 0.2f * sc;
        m = fmaxf(m, sc);
    }
    #pragma unroll
    for (int o = 16; o > 0; o >>= 1) m = fmaxf(m, __shfl_xor_sync(FULL_MASK, m, o));

    float acc[8] = {0.f, 0.f, 0.f, 0.f, 0.f, 0.f, 0.f, 0.f};
    float denom = 0.f;
    for (int base = start; base < end; base += 32) {
        int i = base + lane;
        float w = 0.f;
        int s = 0;
        if (i < end) {
            s = g_csr[i];
            float sc = sum4(&g_ssrcp[(size_t)s * 4]) + sd;
            sc = sc > 0.f ? sc : 0.2f * sc;
            w = __expf(sc - m);
        }
        denom += w;
        int cnt = min(32, end - base);
        int j = 0;
        for (; j + 1 < cnt; j += 2) {
            float w0 = __shfl_sync(FULL_MASK, w, j);
            int   s0 = __shfl_sync(FULL_MASK, s, j);
            float w1 = __shfl_sync(FULL_MASK, w, j + 1);
            int   s1 = __shfl_sync(FULL_MASK, s, j + 1);
            const float4* p0 = reinterpret_cast<const float4*>(h + (size_t)s0 * HID);
            const float4* p1 = reinterpret_cast<const float4*>(h + (size_t)s1 * HID);
            float4 a0 = p0[lane * 2],     b0 = p1[lane * 2];
            float4 a1 = p0[lane * 2 + 1], b1 = p1[lane * 2 + 1];
            acc[0] += w0 * a0.x + w1 * b0.x; acc[1] += w0 * a0.y + w1 * b0.y;
            acc[2] += w0 * a0.z + w1 * b0.z; acc[3] += w0 * a0.w + w1 * b0.w;
            acc[4] += w0 * a1.x + w1 * b1.x; acc[5] += w0 * a1.y + w1 * b1.y;
            acc[6] += w0 * a1.z + w1 * b1.z; acc[7] += w0 * a1.w + w1 * b1.w;
        }
        if (j < cnt) {
            float w0 = __shfl_sync(FULL_MASK, w, j);
            int   s0 = __shfl_sync(FULL_MASK, s, j);
            const float4* p0 = reinterpret_cast<const float4*>(h + (size_t)s0 * HID);
            float4 a0 = p0[lane * 2];
            float4 a1 = p0[lane * 2 + 1];
            acc[0] += w0 * a0.x; acc[1] += w0 * a0.y;
            acc[2] += w0 * a0.z; acc[3] += w0 * a0.w;
            acc[4] += w0 * a1.x; acc[5] += w0 * a1.y;
            acc[6] += w0 * a1.z; acc[7] += w0 * a1.w;
        }
    }
    #pragma unroll
    for (int o = 16; o > 0; o >>= 1) denom += __shfl_xor_sync(FULL_MASK, denom, o);
    float inv = 1.f / (denom + 1e-16f);

    const float4* bq = reinterpret_cast<const float4*>(bias + lane * 8);
    float4 b0 = bq[0], b1 = bq[1];
    float bvals[8] = {b0.x, b0.y, b0.z, b0.w, b1.x, b1.y, b1.z, b1.w};
    __nv_bfloat16 hbuf[8], lbuf[8];
    #pragma unroll
    for (int k = 0; k < 8; k++) {
        float v = acc[k] * inv + bvals[k];
        if (RELU) v = fmaxf(v, 0.f);
        hbuf[k] = __float2bfloat16_rn(v);
        lbuf[k] = __float2bfloat16_rn(v - __bfloat162float(hbuf[k]));
    }
    __nv_bfloat16* op = outExp + (size_t)d * KT + lane * 8;
    *reinterpret_cast<uint4*>(op)       = *reinterpret_cast<uint4*>(hbuf);
    *reinterpret_cast<uint4*>(op + 256) = *reinterpret_cast<uint4*>(hbuf);
    *reinterpret_cast<uint4*>(op + 512) = *reinterpret_cast<uint4*>(lbuf);
}

// ---------------- launch ------------------------------------------------------
extern "C" void kernel_launch(void* const* d_in, const int* in_sizes, int n_in,
                              void* d_out, int out_size) {
    const float* x    = (const float*)d_in[0];
    const void*  edge = d_in[1];
    const float* as1 = (const float*)d_in[3];
    const float* ad1 = (const float*)d_in[4];
    const float* b1 = (const float*)d_in[5];
    const float* as2 = (const float*)d_in[7];
    const float* ad2 = (const float*)d_in[8];
    const float* b2 = (const float*)d_in[9];
    const float* as3 = (const float*)d_in[11];
    const float* ad3 = (const float*)d_in[12];
    const float* b3 = (const float*)d_in[13];
    const float* bp = (const float*)d_in[15];
    const float* br = (const float*)d_in[17];
    float* out = (float*)d_out;

    int E = in_sizes[1] / 2;

    float* h;
    __nv_bfloat16 *aexp, *aexp2, *wexp;
    cudaGetSymbolAddress((void**)&h,     g_h);
    cudaGetSymbolAddress((void**)&aexp,  g_aexp);
    cudaGetSymbolAddress((void**)&aexp2, g_aexp2);
    cudaGetSymbolAddress((void**)&wexp,  g_wexp);

    const int TPB = 256;
    const int SMEM = 3 * 2 * 128 * 40 * 2;   // 61440 B (3-stage double tiles)
    cudaFuncSetAttribute(gemm_bf16<0, false, false, true>,
                         cudaFuncAttributeMaxDynamicSharedMemorySize, SMEM);
    cudaFuncSetAttribute(gemm_bf16<1, true, true, false>,
                         cudaFuncAttributeMaxDynamicSharedMemorySize, SMEM);
    cudaFuncSetAttribute(gemm_bf16<0, true, false, false>,
                         cudaFuncAttributeMaxDynamicSharedMemorySize, SMEM);

    int nodeBlocks = (N_NODES + TPB - 1) / TPB;
    int warpNodeBlocks = (N_NODES * 32 + TPB - 1) / TPB;
    int scanBlocks = (N_NODES + 1023) / 1024;

    dim3 gH((N_NODES + 127) / 128, 2);
    dim3 gR((N_NODES + 127) / 128, 1);

    // init + converts
    detect_kernel<<<1, 32>>>(edge, E);
    convert_split_kernel<<<(N_NODES * 32 + TPB - 1) / TPB, TPB>>>(x, aexp, N_NODES);
    convert_w_all<<<(4 * 65536 + 256 * 40 + TPB - 1) / TPB, TPB>>>(
        (const float*)d_in[2], (const float*)d_in[6], (const float*)d_in[10],
        (const float*)d_in[14], (const float*)d_in[16]);

    // GEMM layer 1 (fused scores, slot stores)  <- ncu sampling slot
    gemm_bf16<0, false, false, true><<<gH, TPB, SMEM>>>(
        aexp, wexp, nullptr, h, nullptr, as1, ad1, N_NODES, 256);

    // CSR build (independent of GEMM result; deg starts at rest-state zero)
    hist_kernel<<<(E + TPB - 1) / TPB, TPB>>>(edge, E);
    scan1_kernel<<<scanBlocks, 1024>>>();
    scan2_kernel<<<1, 64>>>(scanBlocks);
    scan3_kernel<<<nodeBlocks, TPB>>>();
    scatter_kernel<<<(E + N_NODES + TPB - 1) / TPB, TPB>>>(edge, E);

    // layer 1 aggregate
    aggregate_kernel<true><<<warpNodeBlocks, TPB>>>(h, b1, aexp);

    // layer 2
    gemm_bf16<0, false, false, true><<<gH, TPB, SMEM>>>(
        aexp, wexp + WSLOT, nullptr, h, nullptr, as2, ad2, N_NODES, 256);
    aggregate_kernel<true><<<warpNodeBlocks, TPB>>>(h, b2, aexp);

    // layer 3 (no relu)
    gemm_bf16<0, false, false, true><<<gH, TPB, SMEM>>>(
        aexp, wexp + 2 * WSLOT, nullptr, h, nullptr, as3, ad3, N_NODES, 256);
    aggregate_kernel<false><<<warpNodeBlocks, TPB>>>(h, b3, aexp);

    // post1: Linear + ReLU -> bf16 split
    gemm_bf16<1, true, true, false><<<gH, TPB, SMEM>>>(
        aexp, wexp + 3 * WSLOT, bp, nullptr, aexp2, nullptr, nullptr, N_NODES, 256);
    // readout
    gemm_bf16<0, true, false, false><<<gR, TPB, SMEM>>>(
        aexp2, wexp + 4 * WSLOT, br, out, nullptr, nullptr, nullptr, N_NODES, NCLS);
}

// round 16
// speedup vs baseline: 1.1606x; 1.0244x over previous
#include <cuda_runtime.h>
#include <cuda_bf16.h>
#include <cstdint>

#define N_NODES 50000
#define HID 256
#define NCLS 40
#define E_MAX 1000000
#define KT 768                    // 3 * 256 split-K
#define FULL_MASK 0xFFFFFFFFu
#define WSLOT 196608              // 256*768 bf16 per weight slot

// ---------------- scratch (device globals; no allocations allowed) ----------
__device__ float          g_h[(size_t)N_NODES * HID];      // h = A' @ W' (fp32)
__device__ __nv_bfloat16  g_aexp[(size_t)N_NODES * KT];    // split A operand
__device__ __nv_bfloat16  g_aexp2[(size_t)N_NODES * 512];  // post1 out, compact [hi|lo]
__device__ __nv_bfloat16  g_wexp[4 * WSLOT + 40 * KT];     // all split weights, n-major
__device__ __align__(16) float g_ssrcp[(size_t)4 * N_NODES]; // 4 partials per node
__device__ __align__(16) float g_sdstp[(size_t)4 * N_NODES];
__device__ int   g_deg[N_NODES];                           // zero at rest (scan3 resets)
__device__ int   g_offs[N_NODES + 1];
__device__ int   g_cursor[N_NODES];
__device__ int   g_csr[E_MAX];
__device__ int   g_bsum[64];
__device__ int   g_bbase[64];
__device__ int   g_idx64;

// ---------------- edge index access (dtype-agnostic) ------------------------
__device__ __forceinline__ int edge_val(const void* e, long long i) {
    return g_idx64 ? (int)((const long long*)e)[i] : ((const int*)e)[i];
}

// ---------------- CSR construction ------------------------------------------
__global__ void detect_kernel(const void* edge, int E) {
    if (threadIdx.x == 0) {
        const long long* p = (const long long*)edge;
        int n = E < 1024 ? E : 1024;
        int ok = 1;
        for (int i = 0; i < n; i++) {
            long long v = p[i];
            if (v < 0 || v >= N_NODES) { ok = 0; break; }
        }
        g_idx64 = ok;
    }
}

__global__ void hist_kernel(const void* edge, int E) {
    int i = blockIdx.x * blockDim.x + threadIdx.x;
    if (i < E) atomicAdd(&g_deg[edge_val(edge, (long long)E + i)], 1);
}

__global__ void scan1_kernel() {
    __shared__ int sh[1024];
    int t = threadIdx.x;
    int i = blockIdx.x * 1024 + t;
    int v = (i < N_NODES) ? (g_deg[i] + 1) : 0;   // +1 = self-loop
    sh[t] = v;
    __syncthreads();
    #pragma unroll
    for (int off = 1; off < 1024; off <<= 1) {
        int add = (t >= off) ? sh[t - off] : 0;
        __syncthreads();
        sh[t] += add;
        __syncthreads();
    }
    if (i < N_NODES) g_offs[i] = sh[t] - v;
    if (t == 1023) g_bsum[blockIdx.x] = sh[1023];
}

__global__ void scan2_kernel(int nb) {
    __shared__ int sh[64];
    int t = threadIdx.x;
    int v = (t < nb) ? g_bsum[t] : 0;
    sh[t] = v;
    __syncthreads();
    #pragma unroll
    for (int off = 1; off < 64; off <<= 1) {
        int add = (t >= off) ? sh[t - off] : 0;
        __syncthreads();
        sh[t] += add;
        __syncthreads();
    }
    g_bbase[t] = sh[t] - v;
    if (t == nb - 1) g_offs[N_NODES] = sh[t];
}

// also writes self-loop into slot offs[d]; edge scatter starts at offs[d]+1
__global__ void scan3_kernel() {
    int i = blockIdx.x * blockDim.x + threadIdx.x;
    if (i < N_NODES) {
        int o = g_offs[i] + g_bbase[i >> 10];
        g_offs[i] = o;
        g_csr[o] = i;          // self-loop occupies first slot
        g_cursor[i] = o + 1;
        g_deg[i] = 0;          // reset for next launch (deterministic replays)
    }
}

__global__ void scatter_kernel(const void* edge, int E) {
    int i = blockIdx.x * blockDim.x + threadIdx.x;
    if (i < E) {
        int s = edge_val(edge, i);
        int d = edge_val(edge, (long long)E + i);
        g_csr[atomicAdd(&g_cursor[d], 1)] = s;
    }
}

// ---------------- fused conversions (x split + all weights) ------------------
// A' row layout: [hi(256) | hi(256) | lo(256)]; 8 values/thread, 16B stores.
__global__ void convert_all(const float* __restrict__ X,
                            const float* __restrict__ W1, const float* __restrict__ W2,
                            const float* __restrict__ W3, const float* __restrict__ Wp,
                            const float* __restrict__ Wr,
                            __nv_bfloat16* __restrict__ aexp) {
    int i = blockIdx.x * blockDim.x + threadIdx.x;
    const int NSPLIT = N_NODES * 32;
    if (i < NSPLIT) {
        int row = i >> 5;
        int c8  = (i & 31) * 8;
        const float4* src = reinterpret_cast<const float4*>(X + (size_t)row * 256 + c8);
        float4 v0 = src[0], v1 = src[1];
        float vals[8] = {v0.x, v0.y, v0.z, v0.w, v1.x, v1.y, v1.z, v1.w};
        __nv_bfloat16 hbuf[8], lbuf[8];
        #pragma unroll
        for (int k = 0; k < 8; k++) {
            hbuf[k] = __float2bfloat16_rn(vals[k]);
            lbuf[k] = __float2bfloat16_rn(vals[k] - __bfloat162float(hbuf[k]));
        }
        __nv_bfloat16* r = aexp + (size_t)row * KT + c8;
        *reinterpret_cast<uint4*>(r)       = *reinterpret_cast<uint4*>(hbuf);
        *reinterpret_cast<uint4*>(r + 256) = *reinterpret_cast<uint4*>(hbuf);
        *reinterpret_cast<uint4*>(r + 512) = *reinterpret_cast<uint4*>(lbuf);
        return;
    }
    int j = i - NSPLIT;
    const int SQ = 4 * 65536;
    float v; size_t base; int k;
    if (j < SQ) {
        int m = j >> 16, r = j & 65535;
        const float* W = (m == 0) ? W1 : (m == 1) ? W2 : (m == 2) ? W3 : Wp;
        k = r >> 8;
        int n = r & 255;
        v = W[r];
        base = (size_t)m * WSLOT + (size_t)n * KT;
    } else if (j < SQ + 256 * 40) {
        int r = j - SQ;
        k = r / 40;
        int n = r % 40;
        v = Wr[r];
        base = (size_t)4 * WSLOT + (size_t)n * KT;
    } else return;
    __nv_bfloat16 h = __float2bfloat16_rn(v);
    __nv_bfloat16 l = __float2bfloat16_rn(v - __bfloat162float(h));
    g_wexp[base + k]       = h;
    g_wexp[base + 256 + k] = l;
    g_wexp[base + 512 + k] = h;
}

// ---------------- bf16 tensor-core GEMM (ldmatrix + 3-stage pipeline) --------
__device__ __forceinline__ uint32_t smem_u32(const void* p) {
    uint32_t a;
    asm("{ .reg .u64 t; cvta.to.shared.u64 t, %1; cvt.u32.u64 %0, t; }"
        : "=r"(a) : "l"(p));
    return a;
}

__device__ __forceinline__ void cp16(void* dst, const void* src, int sz) {
    unsigned d = (unsigned)__cvta_generic_to_shared(dst);
    asm volatile("cp.async.cg.shared.global [%0], [%1], 16, %2;\n"
                 :: "r"(d), "l"(src), "r"(sz));
}
#define CP_COMMIT() asm volatile("cp.async.commit_group;\n" ::: "memory")
#define CP_WAIT(n)  asm volatile("cp.async.wait_group %0;\n" :: "n"(n) : "memory")

#define LDSM_X4(r0, r1, r2, r3, addr) \
    asm volatile("ldmatrix.sync.aligned.m8n8.x4.shared.b16 {%0,%1,%2,%3}, [%4];" \
                 : "=r"(r0), "=r"(r1), "=r"(r2), "=r"(r3) : "r"(addr))

__device__ __forceinline__ void mma16816(float* c, const uint32_t* a, const uint32_t* b) {
    asm volatile(
        "mma.sync.aligned.m16n8k16.row.col.f32.bf16.bf16.f32 "
        "{%0,%1,%2,%3}, {%4,%5,%6,%7}, {%8,%9}, {%0,%1,%2,%3};\n"
        : "+f"(c[0]), "+f"(c[1]), "+f"(c[2]), "+f"(c[3])
        : "r"(a[0]), "r"(a[1]), "r"(a[2]), "r"(a[3]), "r"(b[0]), "r"(b[1]));
}

// C[M,Ncols] = A'[M,768] @ W'T[Ncols,768]^T.
// OUTMODE 0: fp32 out; 1: compact bf16 [hi|lo] out (512/row).
// SCORES: per-(y,wn-half) partial row dots to unique slots (no atomics).
// ACOMPACT: A physical layout is [hi|lo] 512/row; logical [hi|hi|lo] via k0 remap.
template <int OUTMODE, bool BIAS, bool RELU, bool SCORES, bool ACOMPACT>
__global__ __launch_bounds__(256)
void gemm_bf16(const __nv_bfloat16* __restrict__ A,
               const __nv_bfloat16* __restrict__ BT,
               const float* __restrict__ bias,
               float* __restrict__ Cf,
               __nv_bfloat16* __restrict__ Cs,
               const float* __restrict__ a_src,
               const float* __restrict__ a_dst,
               int M, int Ncols) {
    constexpr int BK = 32, PITCH = 40;           // 80B row pitch, LDSM conflict-free
    constexpr int STAGE = 2 * 128 * PITCH;       // bf16 elems per stage (A+B)
    constexpr int STAGE_BYTES = STAGE * 2;       // 20480
    constexpr int ASTRIDE = ACOMPACT ? 512 : KT;
    extern __shared__ __align__(16) unsigned char smraw[];
    __nv_bfloat16* sm = reinterpret_cast<__nv_bfloat16*>(smraw);

    int tid = threadIdx.x, lane = tid & 31, wid = tid >> 5;
    int brow = blockIdx.x * 128, bcol = blockIdx.y * 128;
    int wm = (wid & 3) * 32, wn = (wid >> 2) * 64;
    int g = lane >> 2, tq = lane & 3;

    float c[2][8][4];
    #pragma unroll
    for (int i = 0; i < 2; i++)
        #pragma unroll
        for (int j = 0; j < 8; j++)
            #pragma unroll
            for (int q = 0; q < 4; q++) c[i][j][q] = 0.f;

    int lrow = tid >> 1;
    int lck  = (tid & 1) * 16;

    auto loadStage = [&](int st, int k0) {
        __nv_bfloat16* sA = sm + st * STAGE;
        __nv_bfloat16* sB = sA + 128 * PITCH;
        {
            int ka = ACOMPACT ? (k0 < 256 ? k0 : k0 - 256) : k0;
            bool ok = (brow + lrow) < M;
            const __nv_bfloat16* ga = A + (size_t)(brow + lrow) * ASTRIDE + ka + lck;
            int sz = ok ? 16 : 0;
            cp16(&sA[lrow * PITCH + lck],     ok ? (const void*)ga       : (const void*)A, sz);
            cp16(&sA[lrow * PITCH + lck + 8], ok ? (const void*)(ga + 8) : (const void*)A, sz);
        }
        {
            bool ok = (bcol + lrow) < Ncols;
            const __nv_bfloat16* gb = BT + (size_t)(bcol + lrow) * KT + k0 + lck;
            int sz = ok ? 16 : 0;
            cp16(&sB[lrow * PITCH + lck],     ok ? (const void*)gb       : (const void*)BT, sz);
            cp16(&sB[lrow * PITCH + lck + 8], ok ? (const void*)(gb + 8) : (const void*)BT, sz);
        }
    };

    loadStage(0, 0);  CP_COMMIT();
    loadStage(1, BK); CP_COMMIT();

    // ldmatrix per-lane address offsets (bytes within a stage)
    uint32_t smB  = smem_u32(sm);
    uint32_t aOff = (uint32_t)((wm + (lane & 7) + ((lane >> 3) & 1) * 8) * 80)
                    + (uint32_t)(lane >> 4) * 16;
    uint32_t bOff = 10240u
                    + (uint32_t)((wn + (lane & 7) + (lane >> 4) * 8) * 80)
                    + (uint32_t)((lane >> 3) & 1) * 16;

    const int numK = KT / BK;   // 24
    for (int it = 0; it < numK; ++it) {
        CP_WAIT(1);
        __syncthreads();
        if (it + 2 < numK) loadStage((it + 2) % 3, (it + 2) * BK);
        CP_COMMIT();

        uint32_t stBase = smB + (uint32_t)((it % 3) * STAGE_BYTES);
        uint32_t aA = stBase + aOff;
        uint32_t bA = stBase + bOff;

        #pragma unroll
        for (int kk = 0; kk < 2; ++kk) {
            uint32_t ko = kk * 32;   // 16 bf16 = 32 bytes
            uint32_t a[2][4], b[8][2];
            #pragma unroll
            for (int i = 0; i < 2; i++)
                LDSM_X4(a[i][0], a[i][1], a[i][2], a[i][3], aA + i * 1280 + ko);
            #pragma unroll
            for (int jp = 0; jp < 4; jp++) {
                uint32_t r0, r1, r2, r3;
                LDSM_X4(r0, r1, r2, r3, bA + jp * 1280 + ko);
                b[2 * jp][0]     = r0; b[2 * jp][1]     = r1;
                b[2 * jp + 1][0] = r2; b[2 * jp + 1][1] = r3;
            }
            #pragma unroll
            for (int i = 0; i < 2; i++)
                #pragma unroll
                for (int j = 0; j < 8; j++) mma16816(c[i][j], a[i], b[j]);
        }
    }

    // ---- epilogue ----
    float asv[8][2], adv[8][2];
    if (SCORES) {
        #pragma unroll
        for (int j = 0; j < 8; j++) {
            int gc = bcol + wn + 8 * j + 2 * tq;
            asv[j][0] = a_src[gc]; asv[j][1] = a_src[gc + 1];
            adv[j][0] = a_dst[gc]; adv[j][1] = a_dst[gc + 1];
        }
    }
    int slot = blockIdx.y * 2 + (wid >> 2);   // unique writer per (slot, row)
    #pragma unroll
    for (int i = 0; i < 2; i++) {
        #pragma unroll
        for (int half = 0; half < 2; half++) {
            int gr = brow + wm + 16 * i + 8 * half + g;
            bool ok = gr < M;
            float ps = 0.f, pd = 0.f;
            #pragma unroll
            for (int j = 0; j < 8; j++) {
                int gc = bcol + wn + 8 * j + 2 * tq;
                float v0 = c[i][j][half * 2 + 0];
                float v1 = c[i][j][half * 2 + 1];
                if (BIAS) { v0 += bias[gc]; v1 += (gc + 1 < Ncols) ? bias[gc + 1] : 0.f; }
                if (RELU) { v0 = fmaxf(v0, 0.f); v1 = fmaxf(v1, 0.f); }
                if (SCORES) {
                    ps += v0 * asv[j][0] + v1 * asv[j][1];
                    pd += v0 * adv[j][0] + v1 * adv[j][1];
                }
                if (ok) {
                    if (OUTMODE == 0) {
                        if (gc + 1 < Ncols) {
                            *reinterpret_cast<float2*>(Cf + (size_t)gr * Ncols + gc) =
                                make_float2(v0, v1);
                        } else if (gc < Ncols) {
                            Cf[(size_t)gr * Ncols + gc] = v0;
                        }
                    } else {
                        __nv_bfloat16 h0 = __float2bfloat16_rn(v0);
                        __nv_bfloat16 h1 = __float2bfloat16_rn(v1);
                        __nv_bfloat162 hi; hi.x = h0; hi.y = h1;
                        __nv_bfloat162 lo;
                        lo.x = __float2bfloat16_rn(v0 - __bfloat162float(h0));
                        lo.y = __float2bfloat16_rn(v1 - __bfloat162float(h1));
                        __nv_bfloat16* r = Cs + (size_t)gr * 512 + gc;   // compact [hi|lo]
                        *reinterpret_cast<__nv_bfloat162*>(r)       = hi;
                        *reinterpret_cast<__nv_bfloat162*>(r + 256) = lo;
                    }
                }
            }
            if (SCORES) {
                ps += __shfl_xor_sync(FULL_MASK, ps, 1);
                ps += __shfl_xor_sync(FULL_MASK, ps, 2);
                pd += __shfl_xor_sync(FULL_MASK, pd, 1);
                pd += __shfl_xor_sync(FULL_MASK, pd, 2);
                if (tq == 0 && ok) {
                    g_ssrcp[(size_t)gr * 4 + slot] = ps;
                    g_sdstp[(size_t)gr * 4 + slot] = pd;
                }
            }
        }
    }
}

// ---------------- GAT aggregation: one warp per dst; emits bf16 split --------
__device__ __forceinline__ float sum4(const float* p) {
    float4 v = *reinterpret_cast<const float4*>(p);
    return (v.x + v.y) + (v.z + v.w);
}

template <bool RELU>
__global__ void aggregate_kernel(const float* __restrict__ h,
                                 const float* __restrict__ bias,
                                 __nv_bfloat16* __restrict__ outExp) {
    int d    = (blockIdx.x * blockDim.x + threadIdx.x) >> 5;
    int lane = threadIdx.x & 31;
    if (d >= N_NODES) return;
    int start = g_offs[d];
    int end   = g_offs[d + 1];
    float sd  = sum4(&g_sdstp[(size_t)d * 4]);

    float m = -1e30f;
    for (int i = start + lane; i < end; i += 32) {
        int s = g_csr[i];
        float sc = sum4(&g_ssrcp[(size_t)s * 4]) + sd;
        sc = sc > 0.f ? sc : 0.2f * sc;
        m = fmaxf(m, sc);
    }
    #pragma unroll
    for (int o = 16; o > 0; o >>= 1) m = fmaxf(m, __shfl_xor_sync(FULL_MASK, m, o));

    float acc[8] = {0.f, 0.f, 0.f, 0.f, 0.f, 0.f, 0.f, 0.f};
    float denom = 0.f;
    for (int base = start; base < end; base += 32) {
        int i = base + lane;
        float w = 0.f;
        int s = 0;
        if (i < end) {
            s = g_csr[i];
            float sc = sum4(&g_ssrcp[(size_t)s * 4]) + sd;
            sc = sc > 0.f ? sc : 0.2f * sc;
            w = __expf(sc - m);
        }
        denom += w;
        int cnt = min(32, end - base);
        int j = 0;
        for (; j + 1 < cnt; j += 2) {
            float w0 = __shfl_sync(FULL_MASK, w, j);
            int   s0 = __shfl_sync(FULL_MASK, s, j);
            float w1 = __shfl_sync(FULL_MASK, w, j + 1);
            int   s1 = __shfl_sync(FULL_MASK, s, j + 1);
            const float4* p0 = reinterpret_cast<const float4*>(h + (size_t)s0 * HID);
            const float4* p1 = reinterpret_cast<const float4*>(h + (size_t)s1 * HID);
            float4 a0 = p0[lane * 2],     b0 = p1[lane * 2];
            float4 a1 = p0[lane * 2 + 1], b1 = p1[lane * 2 + 1];
            acc[0] += w0 * a0.x + w1 * b0.x; acc[1] += w0 * a0.y + w1 * b0.y;
            acc[2] += w0 * a0.z + w1 * b0.z; acc[3] += w0 * a0.w + w1 * b0.w;
            acc[4] += w0 * a1.x + w1 * b1.x; acc[5] += w0 * a1.y + w1 * b1.y;
            acc[6] += w0 * a1.z + w1 * b1.z; acc[7] += w0 * a1.w + w1 * b1.w;
        }
        if (j < cnt) {
            float w0 = __shfl_sync(FULL_MASK, w, j);
            int   s0 = __shfl_sync(FULL_MASK, s, j);
            const float4* p0 = reinterpret_cast<const float4*>(h + (size_t)s0 * HID);
            float4 a0 = p0[lane * 2];
            float4 a1 = p0[lane * 2 + 1];
            acc[0] += w0 * a0.x; acc[1] += w0 * a0.y;
            acc[2] += w0 * a0.z; acc[3] += w0 * a0.w;
            acc[4] += w0 * a1.x; acc[5] += w0 * a1.y;
            acc[6] += w0 * a1.z; acc[7] += w0 * a1.w;
        }
    }
    #pragma unroll
    for (int o = 16; o > 0; o >>= 1) denom += __shfl_xor_sync(FULL_MASK, denom, o);
    float inv = 1.f / (denom + 1e-16f);

    const float4* bq = reinterpret_cast<const float4*>(bias + lane * 8);
    float4 b0 = bq[0], b1 = bq[1];
    float bvals[8] = {b0.x, b0.y, b0.z, b0.w, b1.x, b1.y, b1.z, b1.w};
    __nv_bfloat16 hbuf[8], lbuf[8];
    #pragma unroll
    for (int k = 0; k < 8; k++) {
        float v = acc[k] * inv + bvals[k];
        if (RELU) v = fmaxf(v, 0.f);
        hbuf[k] = __float2bfloat16_rn(v);
        lbuf[k] = __float2bfloat16_rn(v - __bfloat162float(hbuf[k]));
    }
    __nv_bfloat16* op = outExp + (size_t)d * KT + lane * 8;
    *reinterpret_cast<uint4*>(op)       = *reinterpret_cast<uint4*>(hbuf);
    *reinterpret_cast<uint4*>(op + 256) = *reinterpret_cast<uint4*>(hbuf);
    *reinterpret_cast<uint4*>(op + 512) = *reinterpret_cast<uint4*>(lbuf);
}

// ---------------- launch ------------------------------------------------------
extern "C" void kernel_launch(void* const* d_in, const int* in_sizes, int n_in,
                              void* d_out, int out_size) {
    const float* x    = (const float*)d_in[0];
    const void*  edge = d_in[1];
    const float* as1 = (const float*)d_in[3];
    const float* ad1 = (const float*)d_in[4];
    const float* b1 = (const float*)d_in[5];
    const float* as2 = (const float*)d_in[7];
    const float* ad2 = (const float*)d_in[8];
    const float* b2 = (const float*)d_in[9];
    const float* as3 = (const float*)d_in[11];
    const float* ad3 = (const float*)d_in[12];
    const float* b3 = (const float*)d_in[13];
    const float* bp = (const float*)d_in[15];
    const float* br = (const float*)d_in[17];
    float* out = (float*)d_out;

    int E = in_sizes[1] / 2;

    float* h;
    __nv_bfloat16 *aexp, *aexp2, *wexp;
    cudaGetSymbolAddress((void**)&h,     g_h);
    cudaGetSymbolAddress((void**)&aexp,  g_aexp);
    cudaGetSymbolAddress((void**)&aexp2, g_aexp2);
    cudaGetSymbolAddress((void**)&wexp,  g_wexp);

    const int TPB = 256;
    const int SMEM = 3 * 2 * 128 * 40 * 2;   // 61440 B (3-stage double tiles)
    cudaFuncSetAttribute(gemm_bf16<0, false, false, true, false>,
                         cudaFuncAttributeMaxDynamicSharedMemorySize, SMEM);
    cudaFuncSetAttribute(gemm_bf16<1, true, true, false, false>,
                         cudaFuncAttributeMaxDynamicSharedMemorySize, SMEM);
    cudaFuncSetAttribute(gemm_bf16<0, true, false, false, true>,
                         cudaFuncAttributeMaxDynamicSharedMemorySize, SMEM);

    int nodeBlocks = (N_NODES + TPB - 1) / TPB;
    int warpNodeBlocks = (N_NODES * 32 + TPB - 1) / TPB;
    int scanBlocks = (N_NODES + 1023) / 1024;
    int convThreads = N_NODES * 32 + 4 * 65536 + 256 * 40;

    dim3 gH((N_NODES + 127) / 128, 2);
    dim3 gR((N_NODES + 127) / 128, 1);

    // init + fused converts
    detect_kernel<<<1, 32>>>(edge, E);
    convert_all<<<(convThreads + TPB - 1) / TPB, TPB>>>(
        x, (const float*)d_in[2], (const float*)d_in[6], (const float*)d_in[10],
        (const float*)d_in[14], (const float*)d_in[16], aexp);

    // GEMM layer 1 (fused scores, slot stores)  <- ncu sampling slot
    gemm_bf16<0, false, false, true, false><<<gH, TPB, SMEM>>>(
        aexp, wexp, nullptr, h, nullptr, as1, ad1, N_NODES, 256);

    // CSR build (independent of GEMM result; deg starts at rest-state zero)
    hist_kernel<<<(E + TPB - 1) / TPB, TPB>>>(edge, E);
    scan1_kernel<<<scanBlocks, 1024>>>();
    scan2_kernel<<<1, 64>>>(scanBlocks);
    scan3_kernel<<<nodeBlocks, TPB>>>();
    scatter_kernel<<<(E + TPB - 1) / TPB, TPB>>>(edge, E);

    // layer 1 aggregate
    aggregate_kernel<true><<<warpNodeBlocks, TPB>>>(h, b1, aexp);

    // layer 2
    gemm_bf16<0, false, false, true, false><<<gH, TPB, SMEM>>>(
        aexp, wexp + WSLOT, nullptr, h, nullptr, as2, ad2, N_NODES, 256);
    aggregate_kernel<true><<<warpNodeBlocks, TPB>>>(h, b2, aexp);

    // layer 3 (no relu)
    gemm_bf16<0, false, false, true, false><<<gH, TPB, SMEM>>>(
        aexp, wexp + 2 * WSLOT, nullptr, h, nullptr, as3, ad3, N_NODES, 256);
    aggregate_kernel<false><<<warpNodeBlocks, TPB>>>(h, b3, aexp);

    // post1: Linear + ReLU -> compact bf16 [hi|lo]
    gemm_bf16<1, true, true, false, false><<<gH, TPB, SMEM>>>(
        aexp, wexp + 3 * WSLOT, bp, nullptr, aexp2, nullptr, nullptr, N_NODES, 256);
    // readout: compact-A remap reconstructs [hi|hi|lo]
    gemm_bf16<0, true, false, false, true><<<gR, TPB, SMEM>>>(
        aexp2, wexp + 4 * WSLOT, br, out, nullptr, nullptr, nullptr, N_NODES, NCLS);
}

// round 17
// speedup vs baseline: 1.2103x; 1.0428x over previous
#include <cuda_runtime.h>
#include <cuda_bf16.h>
#include <cstdint>

#define N_NODES 50000
#define HID 256
#define NCLS 40
#define E_MAX 1000000
#define KT 768                    // logical split-K (3 * 256)
#define ACOMP 512                 // physical compact A stride [hi|lo]
#define FULL_MASK 0xFFFFFFFFu
#define WSLOT 196608              // 256*768 bf16 per weight slot

// ---------------- scratch (device globals; no allocations allowed) ----------
__device__ float          g_h[(size_t)N_NODES * HID];      // h = A' @ W' (fp32)
__device__ __nv_bfloat16  g_aexp[(size_t)N_NODES * ACOMP]; // compact split A [hi|lo]
__device__ __nv_bfloat16  g_aexp2[(size_t)N_NODES * ACOMP];// post1 out, compact [hi|lo]
__device__ __nv_bfloat16  g_wexp[4 * WSLOT + 40 * KT];     // all split weights, n-major
__device__ __align__(16) float g_ssrcp[(size_t)4 * N_NODES]; // 4 partials per node
__device__ __align__(16) float g_sdstp[(size_t)4 * N_NODES];
__device__ int   g_deg[N_NODES];                           // zero at rest (scan3 resets)
__device__ int   g_offs[N_NODES + 1];
__device__ int   g_cursor[N_NODES];
__device__ int   g_csr[E_MAX];
__device__ int   g_bsum[64];
__device__ int   g_bbase[64];
__device__ int   g_idx64;

// ---------------- edge index access (dtype-agnostic) ------------------------
__device__ __forceinline__ int edge_val(const void* e, long long i) {
    return g_idx64 ? (int)((const long long*)e)[i] : ((const int*)e)[i];
}

// ---------------- CSR construction ------------------------------------------
__global__ void detect_kernel(const void* edge, int E) {
    if (threadIdx.x == 0) {
        const long long* p = (const long long*)edge;
        int n = E < 1024 ? E : 1024;
        int ok = 1;
        for (int i = 0; i < n; i++) {
            long long v = p[i];
            if (v < 0 || v >= N_NODES) { ok = 0; break; }
        }
        g_idx64 = ok;
    }
}

__global__ void hist_kernel(const void* edge, int E) {
    int i = blockIdx.x * blockDim.x + threadIdx.x;
    if (i < E) atomicAdd(&g_deg[edge_val(edge, (long long)E + i)], 1);
}

__global__ void scan1_kernel() {
    __shared__ int sh[1024];
    int t = threadIdx.x;
    int i = blockIdx.x * 1024 + t;
    int v = (i < N_NODES) ? (g_deg[i] + 1) : 0;   // +1 = self-loop
    sh[t] = v;
    __syncthreads();
    #pragma unroll
    for (int off = 1; off < 1024; off <<= 1) {
        int add = (t >= off) ? sh[t - off] : 0;
        __syncthreads();
        sh[t] += add;
        __syncthreads();
    }
    if (i < N_NODES) g_offs[i] = sh[t] - v;
    if (t == 1023) g_bsum[blockIdx.x] = sh[1023];
}

__global__ void scan2_kernel(int nb) {
    __shared__ int sh[64];
    int t = threadIdx.x;
    int v = (t < nb) ? g_bsum[t] : 0;
    sh[t] = v;
    __syncthreads();
    #pragma unroll
    for (int off = 1; off < 64; off <<= 1) {
        int add = (t >= off) ? sh[t - off] : 0;
        __syncthreads();
        sh[t] += add;
        __syncthreads();
    }
    g_bbase[t] = sh[t] - v;
    if (t == nb - 1) g_offs[N_NODES] = sh[t];
}

// also writes self-loop into slot offs[d]; edge scatter starts at offs[d]+1
__global__ void scan3_kernel() {
    int i = blockIdx.x * blockDim.x + threadIdx.x;
    if (i < N_NODES) {
        int o = g_offs[i] + g_bbase[i >> 10];
        g_offs[i] = o;
        g_csr[o] = i;          // self-loop occupies first slot
        g_cursor[i] = o + 1;
        g_deg[i] = 0;          // reset for next launch (deterministic replays)
    }
}

__global__ void scatter_kernel(const void* edge, int E) {
    int i = blockIdx.x * blockDim.x + threadIdx.x;
    if (i < E) {
        int s = edge_val(edge, i);
        int d = edge_val(edge, (long long)E + i);
        g_csr[atomicAdd(&g_cursor[d], 1)] = s;
    }
}

// ---------------- fused conversions (x split + all weights) ------------------
// Compact A row: [hi(256) | lo(256)]; 8 values/thread, 16B stores.
__global__ void convert_all(const float* __restrict__ X,
                            const float* __restrict__ W1, const float* __restrict__ W2,
                            const float* __restrict__ W3, const float* __restrict__ Wp,
                            const float* __restrict__ Wr,
                            __nv_bfloat16* __restrict__ aexp) {
    int i = blockIdx.x * blockDim.x + threadIdx.x;
    const int NSPLIT = N_NODES * 32;
    if (i < NSPLIT) {
        int row = i >> 5;
        int c8  = (i & 31) * 8;
        const float4* src = reinterpret_cast<const float4*>(X + (size_t)row * 256 + c8);
        float4 v0 = src[0], v1 = src[1];
        float vals[8] = {v0.x, v0.y, v0.z, v0.w, v1.x, v1.y, v1.z, v1.w};
        __nv_bfloat16 hbuf[8], lbuf[8];
        #pragma unroll
        for (int k = 0; k < 8; k++) {
            hbuf[k] = __float2bfloat16_rn(vals[k]);
            lbuf[k] = __float2bfloat16_rn(vals[k] - __bfloat162float(hbuf[k]));
        }
        __nv_bfloat16* r = aexp + (size_t)row * ACOMP + c8;
        *reinterpret_cast<uint4*>(r)       = *reinterpret_cast<uint4*>(hbuf);
        *reinterpret_cast<uint4*>(r + 256) = *reinterpret_cast<uint4*>(lbuf);
        return;
    }
    int j = i - NSPLIT;
    const int SQ = 4 * 65536;
    float v; size_t base; int k;
    if (j < SQ) {
        int m = j >> 16, r = j & 65535;
        const float* W = (m == 0) ? W1 : (m == 1) ? W2 : (m == 2) ? W3 : Wp;
        k = r >> 8;
        int n = r & 255;
        v = W[r];
        base = (size_t)m * WSLOT + (size_t)n * KT;
    } else if (j < SQ + 256 * 40) {
        int r = j - SQ;
        k = r / 40;
        int n = r % 40;
        v = Wr[r];
        base = (size_t)4 * WSLOT + (size_t)n * KT;
    } else return;
    __nv_bfloat16 h = __float2bfloat16_rn(v);
    __nv_bfloat16 l = __float2bfloat16_rn(v - __bfloat162float(h));
    g_wexp[base + k]       = h;
    g_wexp[base + 256 + k] = l;
    g_wexp[base + 512 + k] = h;
}

// ---------------- bf16 tensor-core GEMM (ldmatrix + 3-stage pipeline) --------
__device__ __forceinline__ uint32_t smem_u32(const void* p) {
    uint32_t a;
    asm("{ .reg .u64 t; cvta.to.shared.u64 t, %1; cvt.u32.u64 %0, t; }"
        : "=r"(a) : "l"(p));
    return a;
}

__device__ __forceinline__ void cp16(void* dst, const void* src, int sz) {
    unsigned d = (unsigned)__cvta_generic_to_shared(dst);
    asm volatile("cp.async.cg.shared.global [%0], [%1], 16, %2;\n"
                 :: "r"(d), "l"(src), "r"(sz));
}
#define CP_COMMIT() asm volatile("cp.async.commit_group;\n" ::: "memory")
#define CP_WAIT(n)  asm volatile("cp.async.wait_group %0;\n" :: "n"(n) : "memory")

#define LDSM_X4(r0, r1, r2, r3, addr) \
    asm volatile("ldmatrix.sync.aligned.m8n8.x4.shared.b16 {%0,%1,%2,%3}, [%4];" \
                 : "=r"(r0), "=r"(r1), "=r"(r2), "=r"(r3) : "r"(addr))

__device__ __forceinline__ void mma16816(float* c, const uint32_t* a, const uint32_t* b) {
    asm volatile(
        "mma.sync.aligned.m16n8k16.row.col.f32.bf16.bf16.f32 "
        "{%0,%1,%2,%3}, {%4,%5,%6,%7}, {%8,%9}, {%0,%1,%2,%3};\n"
        : "+f"(c[0]), "+f"(c[1]), "+f"(c[2]), "+f"(c[3])
        : "r"(a[0]), "r"(a[1]), "r"(a[2]), "r"(a[3]), "r"(b[0]), "r"(b[1]));
}

// C[M,Ncols] = A'[M,768] @ W'T[Ncols,768]^T.
// A physical layout is compact [hi|lo] 512/row; logical [hi|hi|lo] via k0 remap.
// OUTMODE 0: fp32 out; 1: compact bf16 [hi|lo] out.
// SCORES: per-(y,wn-half) partial row dots to unique slots (no atomics).
template <int OUTMODE, bool BIAS, bool RELU, bool SCORES>
__global__ __launch_bounds__(256)
void gemm_bf16(const __nv_bfloat16* __restrict__ A,
               const __nv_bfloat16* __restrict__ BT,
               const float* __restrict__ bias,
               float* __restrict__ Cf,
               __nv_bfloat16* __restrict__ Cs,
               const float* __restrict__ a_src,
               const float* __restrict__ a_dst,
               int M, int Ncols) {
    constexpr int BK = 32, PITCH = 40;           // 80B row pitch, LDSM conflict-free
    constexpr int STAGE = 2 * 128 * PITCH;       // bf16 elems per stage (A+B)
    constexpr int STAGE_BYTES = STAGE * 2;       // 20480
    extern __shared__ __align__(16) unsigned char smraw[];
    __nv_bfloat16* sm = reinterpret_cast<__nv_bfloat16*>(smraw);

    int tid = threadIdx.x, lane = tid & 31, wid = tid >> 5;
    int brow = blockIdx.x * 128, bcol = blockIdx.y * 128;
    int wm = (wid & 3) * 32, wn = (wid >> 2) * 64;
    int g = lane >> 2, tq = lane & 3;

    float c[2][8][4];
    #pragma unroll
    for (int i = 0; i < 2; i++)
        #pragma unroll
        for (int j = 0; j < 8; j++)
            #pragma unroll
            for (int q = 0; q < 4; q++) c[i][j][q] = 0.f;

    int lrow = tid >> 1;
    int lck  = (tid & 1) * 16;

    auto loadStage = [&](int st, int k0) {
        __nv_bfloat16* sA = sm + st * STAGE;
        __nv_bfloat16* sB = sA + 128 * PITCH;
        {
            int ka = (k0 < 256) ? k0 : k0 - 256;   // [hi|hi|lo] from [hi|lo]
            bool ok = (brow + lrow) < M;
            const __nv_bfloat16* ga = A + (size_t)(brow + lrow) * ACOMP + ka + lck;
            int sz = ok ? 16 : 0;
            cp16(&sA[lrow * PITCH + lck],     ok ? (const void*)ga       : (const void*)A, sz);
            cp16(&sA[lrow * PITCH + lck + 8], ok ? (const void*)(ga + 8) : (const void*)A, sz);
        }
        {
            bool ok = (bcol + lrow) < Ncols;
            const __nv_bfloat16* gb = BT + (size_t)(bcol + lrow) * KT + k0 + lck;
            int sz = ok ? 16 : 0;
            cp16(&sB[lrow * PITCH + lck],     ok ? (const void*)gb       : (const void*)BT, sz);
            cp16(&sB[lrow * PITCH + lck + 8], ok ? (const void*)(gb + 8) : (const void*)BT, sz);
        }
    };

    loadStage(0, 0);  CP_COMMIT();
    loadStage(1, BK); CP_COMMIT();

    // ldmatrix per-lane address offsets (bytes within a stage)
    uint32_t smB  = smem_u32(sm);
    uint32_t aOff = (uint32_t)((wm + (lane & 7) + ((lane >> 3) & 1) * 8) * 80)
                    + (uint32_t)(lane >> 4) * 16;
    uint32_t bOff = 10240u
                    + (uint32_t)((wn + (lane & 7) + (lane >> 4) * 8) * 80)
                    + (uint32_t)((lane >> 3) & 1) * 16;

    const int numK = KT / BK;   // 24
    for (int it = 0; it < numK; ++it) {
        CP_WAIT(1);
        __syncthreads();
        if (it + 2 < numK) loadStage((it + 2) % 3, (it + 2) * BK);
        CP_COMMIT();

        uint32_t stBase = smB + (uint32_t)((it % 3) * STAGE_BYTES);
        uint32_t aA = stBase + aOff;
        uint32_t bA = stBase + bOff;

        #pragma unroll
        for (int kk = 0; kk < 2; ++kk) {
            uint32_t ko = kk * 32;   // 16 bf16 = 32 bytes
            uint32_t a[2][4], b[8][2];
            #pragma unroll
            for (int i = 0; i < 2; i++)
                LDSM_X4(a[i][0], a[i][1], a[i][2], a[i][3], aA + i * 1280 + ko);
            #pragma unroll
            for (int jp = 0; jp < 4; jp++) {
                uint32_t r0, r1, r2, r3;
                LDSM_X4(r0, r1, r2, r3, bA + jp * 1280 + ko);
                b[2 * jp][0]     = r0; b[2 * jp][1]     = r1;
                b[2 * jp + 1][0] = r2; b[2 * jp + 1][1] = r3;
            }
            #pragma unroll
            for (int i = 0; i < 2; i++)
                #pragma unroll
                for (int j = 0; j < 8; j++) mma16816(c[i][j], a[i], b[j]);
        }
    }

    // ---- epilogue ----
    float asv[8][2], adv[8][2];
    if (SCORES) {
        #pragma unroll
        for (int j = 0; j < 8; j++) {
            int gc = bcol + wn + 8 * j + 2 * tq;
            asv[j][0] = a_src[gc]; asv[j][1] = a_src[gc + 1];
            adv[j][0] = a_dst[gc]; adv[j][1] = a_dst[gc + 1];
        }
    }
    int slot = blockIdx.y * 2 + (wid >> 2);   // unique writer per (slot, row)
    #pragma unroll
    for (int i = 0; i < 2; i++) {
        #pragma unroll
        for (int half = 0; half < 2; half++) {
            int gr = brow + wm + 16 * i + 8 * half + g;
            bool ok = gr < M;
            float ps = 0.f, pd = 0.f;
            #pragma unroll
            for (int j = 0; j < 8; j++) {
                int gc = bcol + wn + 8 * j + 2 * tq;
                float v0 = c[i][j][half * 2 + 0];
                float v1 = c[i][j][half * 2 + 1];
                if (BIAS) { v0 += bias[gc]; v1 += (gc + 1 < Ncols) ? bias[gc + 1] : 0.f; }
                if (RELU) { v0 = fmaxf(v0, 0.f); v1 = fmaxf(v1, 0.f); }
                if (SCORES) {
                    ps += v0 * asv[j][0] + v1 * asv[j][1];
                    pd += v0 * adv[j][0] + v1 * adv[j][1];
                }
                if (ok) {
                    if (OUTMODE == 0) {
                        if (gc + 1 < Ncols) {
                            *reinterpret_cast<float2*>(Cf + (size_t)gr * Ncols + gc) =
                                make_float2(v0, v1);
                        } else if (gc < Ncols) {
                            Cf[(size_t)gr * Ncols + gc] = v0;
                        }
                    } else {
                        __nv_bfloat16 h0 = __float2bfloat16_rn(v0);
                        __nv_bfloat16 h1 = __float2bfloat16_rn(v1);
                        __nv_bfloat162 hi; hi.x = h0; hi.y = h1;
                        __nv_bfloat162 lo;
                        lo.x = __float2bfloat16_rn(v0 - __bfloat162float(h0));
                        lo.y = __float2bfloat16_rn(v1 - __bfloat162float(h1));
                        __nv_bfloat16* r = Cs + (size_t)gr * ACOMP + gc;  // compact
                        *reinterpret_cast<__nv_bfloat162*>(r)       = hi;
                        *reinterpret_cast<__nv_bfloat162*>(r + 256) = lo;
                    }
                }
            }
            if (SCORES) {
                ps += __shfl_xor_sync(FULL_MASK, ps, 1);
                ps += __shfl_xor_sync(FULL_MASK, ps, 2);
                pd += __shfl_xor_sync(FULL_MASK, pd, 1);
                pd += __shfl_xor_sync(FULL_MASK, pd, 2);
                if (tq == 0 && ok) {
                    g_ssrcp[(size_t)gr * 4 + slot] = ps;
                    g_sdstp[(size_t)gr * 4 + slot] = pd;
                }
            }
        }
    }
}

// ---------------- GAT aggregation: one warp per dst; emits compact split -----
__device__ __forceinline__ float sum4(const float* p) {
    float4 v = *reinterpret_cast<const float4*>(p);
    return (v.x + v.y) + (v.z + v.w);
}

// weighted gather of one ≤32-edge chunk: lanes hold (w, s); all lanes accumulate
__device__ __forceinline__ void gather_chunk(const float* __restrict__ h,
                                             float w, int s, int cnt, int lane,
                                             float* acc) {
    int j = 0;
    for (; j + 1 < cnt; j += 2) {
        float w0 = __shfl_sync(FULL_MASK, w, j);
        int   s0 = __shfl_sync(FULL_MASK, s, j);
        float w1 = __shfl_sync(FULL_MASK, w, j + 1);
        int   s1 = __shfl_sync(FULL_MASK, s, j + 1);
        const float4* p0 = reinterpret_cast<const float4*>(h + (size_t)s0 * HID);
        const float4* p1 = reinterpret_cast<const float4*>(h + (size_t)s1 * HID);
        float4 a0 = p0[lane * 2],     b0 = p1[lane * 2];
        float4 a1 = p0[lane * 2 + 1], b1 = p1[lane * 2 + 1];
        acc[0] += w0 * a0.x + w1 * b0.x; acc[1] += w0 * a0.y + w1 * b0.y;
        acc[2] += w0 * a0.z + w1 * b0.z; acc[3] += w0 * a0.w + w1 * b0.w;
        acc[4] += w0 * a1.x + w1 * b1.x; acc[5] += w0 * a1.y + w1 * b1.y;
        acc[6] += w0 * a1.z + w1 * b1.z; acc[7] += w0 * a1.w + w1 * b1.w;
    }
    if (j < cnt) {
        float w0 = __shfl_sync(FULL_MASK, w, j);
        int   s0 = __shfl_sync(FULL_MASK, s, j);
        const float4* p0 = reinterpret_cast<const float4*>(h + (size_t)s0 * HID);
        float4 a0 = p0[lane * 2];
        float4 a1 = p0[lane * 2 + 1];
        acc[0] += w0 * a0.x; acc[1] += w0 * a0.y;
        acc[2] += w0 * a0.z; acc[3] += w0 * a0.w;
        acc[4] += w0 * a1.x; acc[5] += w0 * a1.y;
        acc[6] += w0 * a1.z; acc[7] += w0 * a1.w;
    }
}

template <bool RELU>
__global__ void aggregate_kernel(const float* __restrict__ h,
                                 const float* __restrict__ bias,
                                 __nv_bfloat16* __restrict__ outExp) {
    int d    = (blockIdx.x * blockDim.x + threadIdx.x) >> 5;
    int lane = threadIdx.x & 31;
    if (d >= N_NODES) return;
    int start = g_offs[d];
    int end   = g_offs[d + 1];
    int deg   = end - start;
    float sd  = sum4(&g_sdstp[(size_t)d * 4]);

    float acc[8] = {0.f, 0.f, 0.f, 0.f, 0.f, 0.f, 0.f, 0.f};
    float denom;

    if (deg <= 32) {
        // fast path: one score load per edge, kept in registers across phases
        int i = start + lane;
        int s = 0;
        float sc = -1e30f;
        if (i < end) {
            s = g_csr[i];
            sc = sum4(&g_ssrcp[(size_t)s * 4]) + sd;
            sc = sc > 0.f ? sc : 0.2f * sc;
        }
        float m = sc;
        #pragma unroll
        for (int o = 16; o > 0; o >>= 1) m = fmaxf(m, __shfl_xor_sync(FULL_MASK, m, o));
        float w = (i < end) ? __expf(sc - m) : 0.f;
        denom = w;
        gather_chunk(h, w, s, deg, lane, acc);
    } else {
        float m = -1e30f;
        for (int i = start + lane; i < end; i += 32) {
            int s = g_csr[i];
            float sc = sum4(&g_ssrcp[(size_t)s * 4]) + sd;
            sc = sc > 0.f ? sc : 0.2f * sc;
            m = fmaxf(m, sc);
        }
        #pragma unroll
        for (int o = 16; o > 0; o >>= 1) m = fmaxf(m, __shfl_xor_sync(FULL_MASK, m, o));

        denom = 0.f;
        for (int base = start; base < end; base += 32) {
            int i = base + lane;
            float w = 0.f;
            int s = 0;
            if (i < end) {
                s = g_csr[i];
                float sc = sum4(&g_ssrcp[(size_t)s * 4]) + sd;
                sc = sc > 0.f ? sc : 0.2f * sc;
                w = __expf(sc - m);
            }
            denom += w;
            gather_chunk(h, w, s, min(32, end - base), lane, acc);
        }
    }
    #pragma unroll
    for (int o = 16; o > 0; o >>= 1) denom += __shfl_xor_sync(FULL_MASK, denom, o);
    float inv = 1.f / (denom + 1e-16f);

    const float4* bq = reinterpret_cast<const float4*>(bias + lane * 8);
    float4 b0 = bq[0], b1 = bq[1];
    float bvals[8] = {b0.x, b0.y, b0.z, b0.w, b1.x, b1.y, b1.z, b1.w};
    __nv_bfloat16 hbuf[8], lbuf[8];
    #pragma unroll
    for (int k = 0; k < 8; k++) {
        float v = acc[k] * inv + bvals[k];
        if (RELU) v = fmaxf(v, 0.f);
        hbuf[k] = __float2bfloat16_rn(v);
        lbuf[k] = __float2bfloat16_rn(v - __bfloat162float(hbuf[k]));
    }
    __nv_bfloat16* op = outExp + (size_t)d * ACOMP + lane * 8;
    *reinterpret_cast<uint4*>(op)       = *reinterpret_cast<uint4*>(hbuf);
    *reinterpret_cast<uint4*>(op + 256) = *reinterpret_cast<uint4*>(lbuf);
}

// ---------------- launch ------------------------------------------------------
extern "C" void kernel_launch(void* const* d_in, const int* in_sizes, int n_in,
                              void* d_out, int out_size) {
    const float* x    = (const float*)d_in[0];
    const void*  edge = d_in[1];
    const float* as1 = (const float*)d_in[3];
    const float* ad1 = (const float*)d_in[4];
    const float* b1 = (const float*)d_in[5];
    const float* as2 = (const float*)d_in[7];
    const float* ad2 = (const float*)d_in[8];
    const float* b2 = (const float*)d_in[9];
    const float* as3 = (const float*)d_in[11];
    const float* ad3 = (const float*)d_in[12];
    const float* b3 = (const float*)d_in[13];
    const float* bp = (const float*)d_in[15];
    const float* br = (const float*)d_in[17];
    float* out = (float*)d_out;

    int E = in_sizes[1] / 2;

    float* h;
    __nv_bfloat16 *aexp, *aexp2, *wexp;
    cudaGetSymbolAddress((void**)&h,     g_h);
    cudaGetSymbolAddress((void**)&aexp,  g_aexp);
    cudaGetSymbolAddress((void**)&aexp2, g_aexp2);
    cudaGetSymbolAddress((void**)&wexp,  g_wexp);

    const int TPB = 256;
    const int SMEM = 3 * 2 * 128 * 40 * 2;   // 61440 B (3-stage double tiles)
    cudaFuncSetAttribute(gemm_bf16<0, false, false, true>,
                         cudaFuncAttributeMaxDynamicSharedMemorySize, SMEM);
    cudaFuncSetAttribute(gemm_bf16<1, true, true, false>,
                         cudaFuncAttributeMaxDynamicSharedMemorySize, SMEM);
    cudaFuncSetAttribute(gemm_bf16<0, true, false, false>,
                         cudaFuncAttributeMaxDynamicSharedMemorySize, SMEM);

    int nodeBlocks = (N_NODES + TPB - 1) / TPB;
    int warpNodeBlocks = (N_NODES * 32 + TPB - 1) / TPB;
    int scanBlocks = (N_NODES + 1023) / 1024;
    int convThreads = N_NODES * 32 + 4 * 65536 + 256 * 40;

    dim3 gH((N_NODES + 127) / 128, 2);
    dim3 gR((N_NODES + 127) / 128, 1);

    // init + fused converts
    detect_kernel<<<1, 32>>>(edge, E);
    convert_all<<<(convThreads + TPB - 1) / TPB, TPB>>>(
        x, (const float*)d_in[2], (const float*)d_in[6], (const float*)d_in[10],
        (const float*)d_in[14], (const float*)d_in[16], aexp);

    // GEMM layer 1 (fused scores, slot stores)
    gemm_bf16<0, false, false, true><<<gH, TPB, SMEM>>>(
        aexp, wexp, nullptr, h, nullptr, as1, ad1, N_NODES, 256);

    // CSR build (independent of GEMM result; deg starts at rest-state zero)
    hist_kernel<<<(E + TPB - 1) / TPB, TPB>>>(edge, E);
    scan1_kernel<<<scanBlocks, 1024>>>();
    scan2_kernel<<<1, 64>>>(scanBlocks);
    scan3_kernel<<<nodeBlocks, TPB>>>();
    scatter_kernel<<<(E + TPB - 1) / TPB, TPB>>>(edge, E);

    // layer 1 aggregate
    aggregate_kernel<true><<<warpNodeBlocks, TPB>>>(h, b1, aexp);

    // layer 2
    gemm_bf16<0, false, false, true><<<gH, TPB, SMEM>>>(
        aexp, wexp + WSLOT, nullptr, h, nullptr, as2, ad2, N_NODES, 256);
    aggregate_kernel<true><<<warpNodeBlocks, TPB>>>(h, b2, aexp);

    // layer 3 (no relu)
    gemm_bf16<0, false, false, true><<<gH, TPB, SMEM>>>(
        aexp, wexp + 2 * WSLOT, nullptr, h, nullptr, as3, ad3, N_NODES, 256);
    aggregate_kernel<false><<<warpNodeBlocks, TPB>>>(h, b3, aexp);

    // post1: Linear + ReLU -> compact bf16 [hi|lo]
    gemm_bf16<1, true, true, false><<<gH, TPB, SMEM>>>(
        aexp, wexp + 3 * WSLOT, bp, nullptr, aexp2, nullptr, nullptr, N_NODES, 256);
    // readout
    gemm_bf16<0, true, false, false><<<gR, TPB, SMEM>>>(
        aexp2, wexp + 4 * WSLOT, br, out, nullptr, nullptr, nullptr, N_NODES, NCLS);
}